// round 10
// baseline (speedup 1.0000x reference)
#include <cuda_runtime.h>
#include <cuda_bf16.h>
#include <cstdint>

// Shapes (fixed for this problem)
#define N_TOTAL (64 * 4096)      // 262144 nodes
#define NHID    128
#define NN      4096             // nodes per graph == w3 dim
#define MB      64               // batch (graphs)

// table for s(f,g), t(f,g): range [-6,6]^2, h = 3/32, 129x129 points
#define TAB_N    129
#define TAB_LO   (-6.0f)
#define TAB_INVH (32.0f / 3.0f)

// ---------------- scratch (device globals; no allocation allowed) ----------
__device__ __align__(16) float2 g_fd [N_TOTAL];   // {agg1, deg} interleaved
__device__ __align__(16) float g_s   [N_TOTAL];
__device__ __align__(16) float g_t   [N_TOTAL];
__device__ __align__(16) float g_agg2[N_TOTAL];
#define GEMM_KSPLIT 8
__device__ float g_part[GEMM_KSPLIT * N_TOTAL];        // split-K partials (8MB)
__device__ __align__(16) unsigned short g_Ah[N_TOTAL]; // A bf16 hi
__device__ __align__(16) unsigned short g_Al[N_TOTAL]; // A bf16 lo
__device__ __align__(16) float2 g_tab[TAB_N * TAB_N];  // {s,t} table (133KB)

#define C_2LOG2E 2.88539008177792681f   // 2*log2(e)

__device__ __forceinline__ float ex2f(float x) {
    float e; asm("ex2.approx.f32 %0, %1;" : "=f"(e) : "f"(x)); return e;
}
__device__ __forceinline__ float rcpf(float x) {
    float r; asm("rcp.approx.f32 %0, %1;" : "=f"(r) : "f"(x)); return r;
}
// tanh from prescaled xp = 2*log2e*x : tanh = 1 - 2/(exp2(xp)+1)
__device__ __forceinline__ float tanh_exp2(float xp) {
    return fmaf(-2.0f, rcpf(ex2f(xp) + 1.0f), 1.0f);
}

// fast hi/lo bf16 split of two floats: hi = truncation (PRMT pack),
// lo = exact residual rounded to bf16 (packed cvt). 6 ops / 2 floats.
__device__ __forceinline__ void split2_fast(float a, float b,
                                            uint32_t& hi, uint32_t& lo) {
    uint32_t ua = __float_as_uint(a), ub = __float_as_uint(b);
    hi = __byte_perm(ua, ub, 0x7632);                   // {a_hi16, b_hi16}
    float ah = __uint_as_float(ua & 0xFFFF0000u);
    float bh = __uint_as_float(ub & 0xFFFF0000u);
    float la = a - ah, lb = b - bh;
    asm("cvt.rn.satfinite.bf16x2.f32 %0, %1, %2;" : "=r"(lo) : "f"(lb), "f"(la));
}

// ---------------- side-branch: build s/t table (footprint-light) ------------
__global__ void k_tab(const float* __restrict__ ws1, const float* __restrict__ wn1,
                      const float* __restrict__ b1,
                      const float* __restrict__ ws2, const float* __restrict__ wn2) {
    int p = blockIdx.x * blockDim.x + threadIdx.x;
    if (p >= TAB_N * TAB_N) return;
    int fi = p % TAB_N, gi = p / TAB_N;
    float f = TAB_LO + fi * (1.0f / TAB_INVH);
    float g = TAB_LO + gi * (1.0f / TAB_INVH);
    float s = 0.0f, t = 0.0f;
#pragma unroll 4
    for (int j = 0; j < NHID; j++) {
        float xp = C_2LOG2E * fmaf(f, __ldg(&ws1[j]),
                                   fmaf(g, __ldg(&wn1[j]), __ldg(&b1[j])));
        float r = tanh_exp2(xp);
        s = fmaf(r, __ldg(&ws2[j]), s);
        t = fmaf(r, __ldg(&wn2[j]), t);
    }
    g_tab[p] = make_float2(s, t);
}

// ---------------- kernel 0: zero scratch (vectorized) -----------------------
__global__ void k_zero(int n4) {   // n4 = N_TOTAL/4
    int i = blockIdx.x * blockDim.x + threadIdx.x;
    if (i < n4) {
        float4 z = make_float4(0.f, 0.f, 0.f, 0.f);
        reinterpret_cast<float4*>(g_fd)[2 * i]     = z;
        reinterpret_cast<float4*>(g_fd)[2 * i + 1] = z;
        reinterpret_cast<float4*>(g_agg2)[i]       = z;
    }
}

// ---------------- kernel 1: edge scatter pass 1 ({agg1,deg} v2 red) ---------
__global__ void k_edge1(const float* __restrict__ feat,
                        const int* __restrict__ src,
                        const int* __restrict__ dst, int E) {
    int e = blockIdx.x * blockDim.x + threadIdx.x;
    if (e < E) {
        int s = src[e];
        int d = dst[e];
        float v = __ldg(&feat[s]);
        asm volatile("red.global.add.v2.f32 [%0], {%1, %2};"
                     :: "l"(g_fd + d), "f"(v), "f"(1.0f) : "memory");
    }
}

// ---------------- kernel 2: s,t via bicubic table lookup (R6 proven) --------
__device__ __forceinline__ void cubic_w(float x, float w[4]) {
    float xm1 = x - 1.0f, xm2 = x - 2.0f, xp1 = x + 1.0f;
    float a = xm1 * xm2;
    float b = xp1 * x;
    w[0] = -x * a * (1.0f / 6.0f);
    w[1] = xp1 * a * 0.5f;
    w[2] = -b * xm2 * 0.5f;
    w[3] = b * xm1 * (1.0f / 6.0f);
}

__global__ __launch_bounds__(256) void k_node1(const float* __restrict__ feat,
                                               int n_total) {
    int n = blockIdx.x * blockDim.x + threadIdx.x;
    if (n >= n_total) return;

    float f   = feat[n];
    float2 fd = g_fd[n];
    float g   = __fdividef(fd.x, fmaxf(fd.y, 1.0f));

    float u = fminf(fmaxf((f - TAB_LO) * TAB_INVH, 1.0f), (float)(TAB_N - 3) - 1e-3f);
    float v = fminf(fmaxf((g - TAB_LO) * TAB_INVH, 1.0f), (float)(TAB_N - 3) - 1e-3f);
    int iu = (int)u;  float x = u - iu;
    int iv = (int)v;  float y = v - iv;

    float wx[4], wy[4];
    cubic_w(x, wx);
    cubic_w(y, wy);

    const float2* base = g_tab + (iv - 1) * TAB_N + (iu - 1);
    float s = 0.0f, t = 0.0f;
#pragma unroll
    for (int a = 0; a < 4; a++) {
        const float2* row = base + a * TAB_N;
        float rs = 0.0f, rt = 0.0f;
#pragma unroll
        for (int b = 0; b < 4; b++) {
            float2 tv = __ldg(&row[b]);
            rs = fmaf(wx[b], tv.x, rs);
            rt = fmaf(wx[b], tv.y, rt);
        }
        s = fmaf(wy[a], rs, s);
        t = fmaf(wy[a], rt, t);
    }
    g_s[n] = s;
    g_t[n] = t;
}

// ---------------- kernel 3: edge scatter pass 2 (agg2 of t) -----------------
__global__ void k_edge2(const int* __restrict__ src,
                        const int* __restrict__ dst, int E) {
    int e = blockIdx.x * blockDim.x + threadIdx.x;
    if (e < E) {
        atomicAdd(&g_agg2[dst[e]], __ldg(&g_t[src[e]]));
    }
}

// ---------------- kernel 4: out1; A = split(tanh(out1)) ---------------------
__global__ void k_node2(const float* __restrict__ b2,
                        float* __restrict__ out, int n_total) {
    int n = blockIdx.x * blockDim.x + threadIdx.x;
    if (n < n_total) {
        float o = g_s[n] + __fdividef(g_agg2[n], fmaxf(g_fd[n].y, 1.0f)) + b2[0];
        out[n] = o;                          // output1
        float h = tanh_exp2(C_2LOG2E * o);
        __nv_bfloat16 hh = __float2bfloat16_rn(h);
        float lo = h - __bfloat162float(hh);
        __nv_bfloat16 hl = __float2bfloat16_rn(lo);
        g_Ah[n] = *reinterpret_cast<unsigned short*>(&hh);
        g_Al[n] = *reinterpret_cast<unsigned short*>(&hl);
    }
}

// ---------------- kernel 5: GEMM partials = h2 @ w3 (bf16 3-pass split) -----
// R6 config (KSPLIT=8, BN=128, 256 blocks) + depth-2 register prefetch,
// with __launch_bounds__(256,2) pinning 2 blocks/SM (<=128 regs) so the
// prefetch cannot cost occupancy. Non-atomic partial stores.
#define GEMM_BN 128
#define GEMM_KRANGE (NN / GEMM_KSPLIT)   // 512
#define GEMM_NCHUNK (GEMM_KRANGE / 16)   // 32

__device__ __forceinline__ void mma_bf16(float c[4], const uint32_t a[4],
                                         const uint32_t b[2]) {
    asm volatile(
        "mma.sync.aligned.m16n8k16.row.col.f32.bf16.bf16.f32 "
        "{%0,%1,%2,%3}, {%4,%5,%6,%7}, {%8,%9}, {%0,%1,%2,%3};\n"
        : "+f"(c[0]), "+f"(c[1]), "+f"(c[2]), "+f"(c[3])
        : "r"(a[0]), "r"(a[1]), "r"(a[2]), "r"(a[3]), "r"(b[0]), "r"(b[1]));
}
__device__ __forceinline__ void ldsm_x4(uint32_t r[4], uint32_t addr) {
    asm volatile("ldmatrix.sync.aligned.m8n8.x4.shared.b16 {%0,%1,%2,%3}, [%4];"
                 : "=r"(r[0]), "=r"(r[1]), "=r"(r[2]), "=r"(r[3]) : "r"(addr));
}
__device__ __forceinline__ void ldsm_x2t(uint32_t r[2], uint32_t addr) {
    asm volatile("ldmatrix.sync.aligned.m8n8.x2.trans.shared.b16 {%0,%1}, [%2];"
                 : "=r"(r[0]), "=r"(r[1]) : "r"(addr));
}

__global__ __launch_bounds__(256, 2) void k_gemm(const float* __restrict__ w3) {
    __shared__ __align__(16) unsigned short sAh[2][MB][16], sAl[2][MB][16];
    __shared__ __align__(16) unsigned short sBh[2][16][GEMM_BN], sBl[2][16][GEMM_BN];

    int tid  = threadIdx.x;
    int warp = tid >> 5;
    int lane = tid & 31;
    int g    = lane >> 2;
    int tg   = lane & 3;
    int n0   = blockIdx.x * GEMM_BN;
    int kb   = blockIdx.y * GEMM_KRANGE;

    int rA = tid >> 2;              // 0..63
    int cA = (tid & 3) * 4;         // ushort col in A tile
    int rB = tid >> 5;              // 0..7 (and +8)
    int cB = (tid & 31) * 4;        // float col in B tile

    float acc[4][2][4];
#pragma unroll
    for (int mi = 0; mi < 4; mi++)
#pragma unroll
        for (int ni = 0; ni < 2; ni++)
#pragma unroll
            for (int r = 0; r < 4; r++) acc[mi][ni][r] = 0.0f;

    // depth-2 register prefetch: slots 0,1 hold chunks ck, ck+1
    uint2 rah[2], ral[2]; float4 rb0[2], rb1[2];
#pragma unroll
    for (int sl = 0; sl < 2; sl++) {
        int k0 = kb + sl * 16;
        rah[sl] = *reinterpret_cast<const uint2*>(&g_Ah[rA * NN + k0 + cA]);
        ral[sl] = *reinterpret_cast<const uint2*>(&g_Al[rA * NN + k0 + cA]);
        rb0[sl] = *reinterpret_cast<const float4*>(&w3[(size_t)(k0 + rB) * NN + n0 + cB]);
        rb1[sl] = *reinterpret_cast<const float4*>(&w3[(size_t)(k0 + rB + 8) * NN + n0 + cB]);
    }

    uint32_t aAh = (uint32_t)__cvta_generic_to_shared(
        &sAh[0][(lane & 15)][(lane >> 4) * 8]);
    uint32_t aAl = (uint32_t)__cvta_generic_to_shared(
        &sAl[0][(lane & 15)][(lane >> 4) * 8]);
    uint32_t aBh = (uint32_t)__cvta_generic_to_shared(
        &sBh[0][(lane & 15)][warp * 16]);
    uint32_t aBl = (uint32_t)__cvta_generic_to_shared(
        &sBl[0][(lane & 15)][warp * 16]);
    const uint32_t strideAbuf = MB * 16 * 2;
    const uint32_t strideBbuf = 16 * GEMM_BN * 2;

#pragma unroll 1
    for (int ck = 0; ck < GEMM_NCHUNK; ck++) {
        int sl = ck & 1;   // reg slot == smem buffer
        {
            *reinterpret_cast<uint2*>(&sAh[sl][rA][cA]) = rah[sl];
            *reinterpret_cast<uint2*>(&sAl[sl][rA][cA]) = ral[sl];
            uint32_t h0, l0, h1, l1;
            split2_fast(rb0[sl].x, rb0[sl].y, h0, l0);
            split2_fast(rb0[sl].z, rb0[sl].w, h1, l1);
            *reinterpret_cast<uint2*>(&sBh[sl][rB][cB]) = make_uint2(h0, h1);
            *reinterpret_cast<uint2*>(&sBl[sl][rB][cB]) = make_uint2(l0, l1);
            split2_fast(rb1[sl].x, rb1[sl].y, h0, l0);
            split2_fast(rb1[sl].z, rb1[sl].w, h1, l1);
            *reinterpret_cast<uint2*>(&sBh[sl][rB + 8][cB]) = make_uint2(h0, h1);
            *reinterpret_cast<uint2*>(&sBl[sl][rB + 8][cB]) = make_uint2(l0, l1);
        }
        if (ck + 2 < GEMM_NCHUNK) {
            int k0 = kb + (ck + 2) * 16;
            rah[sl] = *reinterpret_cast<const uint2*>(&g_Ah[rA * NN + k0 + cA]);
            ral[sl] = *reinterpret_cast<const uint2*>(&g_Al[rA * NN + k0 + cA]);
            rb0[sl] = *reinterpret_cast<const float4*>(&w3[(size_t)(k0 + rB) * NN + n0 + cB]);
            rb1[sl] = *reinterpret_cast<const float4*>(&w3[(size_t)(k0 + rB + 8) * NN + n0 + cB]);
        }
        __syncthreads();

        uint32_t aH[4][4], aL[4][4];
#pragma unroll
        for (int mi = 0; mi < 4; mi++) {
            ldsm_x4(aH[mi], aAh + sl * strideAbuf + mi * 16 * 16 * 2);
            ldsm_x4(aL[mi], aAl + sl * strideAbuf + mi * 16 * 16 * 2);
        }
        uint32_t bH[2][2], bL[2][2];
#pragma unroll
        for (int ni = 0; ni < 2; ni++) {
            ldsm_x2t(bH[ni], aBh + sl * strideBbuf + ni * 8 * 2);
            ldsm_x2t(bL[ni], aBl + sl * strideBbuf + ni * 8 * 2);
        }
#pragma unroll
        for (int mi = 0; mi < 4; mi++)
#pragma unroll
            for (int ni = 0; ni < 2; ni++) {
                mma_bf16(acc[mi][ni], aH[mi], bH[ni]);
                mma_bf16(acc[mi][ni], aH[mi], bL[ni]);
                mma_bf16(acc[mi][ni], aL[mi], bH[ni]);
            }
    }

    float* part = g_part + (size_t)blockIdx.y * N_TOTAL;
#pragma unroll
    for (int mi = 0; mi < 4; mi++) {
        int row = mi * 16 + g;
#pragma unroll
        for (int ni = 0; ni < 2; ni++) {
            int col = n0 + warp * 16 + ni * 8 + 2 * tg;
            *reinterpret_cast<float2*>(&part[(size_t)row * NN + col]) =
                make_float2(acc[mi][ni][0], acc[mi][ni][1]);
            *reinterpret_cast<float2*>(&part[(size_t)(row + 8) * NN + col]) =
                make_float2(acc[mi][ni][2], acc[mi][ni][3]);
        }
    }
}

// ---------------- kernel 6: reduce split-K partials + b3 --------------------
__global__ void k_red(const float* __restrict__ b3,
                      float* __restrict__ out2, int n4) {  // n4 = N_TOTAL/4
    int i = blockIdx.x * blockDim.x + threadIdx.x;
    if (i < n4) {
        float4 a = reinterpret_cast<const float4*>(b3)[i & (NN / 4 - 1)];
#pragma unroll
        for (int j = 0; j < GEMM_KSPLIT; j++) {
            float4 pv = reinterpret_cast<const float4*>(g_part)[(size_t)j * (N_TOTAL / 4) + i];
            a.x += pv.x; a.y += pv.y; a.z += pv.z; a.w += pv.w;
        }
        reinterpret_cast<float4*>(out2)[i] = a;
    }
}

// ---------------- launch ----------------------------------------------------
extern "C" void kernel_launch(void* const* d_in, const int* in_sizes, int n_in,
                              void* d_out, int out_size) {
    const float* feat = (const float*)d_in[0];
    const int*   src  = (const int*)d_in[1];
    const int*   dst  = (const int*)d_in[2];
    const float* ws1  = (const float*)d_in[3];
    const float* wn1  = (const float*)d_in[4];
    const float* b1   = (const float*)d_in[5];
    const float* ws2  = (const float*)d_in[6];
    const float* wn2  = (const float*)d_in[7];
    const float* b2   = (const float*)d_in[8];
    const float* w3   = (const float*)d_in[9];
    const float* b3   = (const float*)d_in[10];
    float* out = (float*)d_out;

    int N = in_sizes[0];   // 262144
    int E = in_sizes[1];   // 2097152

    // side stream: table build only (tiny; overlapped with zero+edge1)
    cudaStream_t s2;
    cudaStreamCreateWithFlags(&s2, cudaStreamNonBlocking);
    cudaEvent_t eF, eJ;
    cudaEventCreateWithFlags(&eF, cudaEventDisableTiming);
    cudaEventCreateWithFlags(&eJ, cudaEventDisableTiming);

    cudaEventRecord(eF, 0);
    cudaStreamWaitEvent(s2, eF, 0);
    k_tab<<<(TAB_N * TAB_N + 255) / 256, 256, 0, s2>>>(ws1, wn1, b1, ws2, wn2);
    cudaEventRecord(eJ, s2);

    k_zero<<<(N / 4 + 255) / 256, 256>>>(N / 4);
    k_edge1<<<(E + 255) / 256, 256>>>(feat, src, dst, E);

    cudaStreamWaitEvent(0, eJ, 0);
    k_node1<<<(N + 255) / 256, 256>>>(feat, N);
    k_edge2<<<(E + 255) / 256, 256>>>(src, dst, E);
    k_node2<<<(N + 255) / 256, 256>>>(b2, out, N);

    dim3 grid(NN / GEMM_BN, GEMM_KSPLIT);
    k_gemm<<<grid, 256>>>(w3);
    k_red<<<(N / 4 + 255) / 256, 256>>>(b3, out + N, N / 4);
}

// round 11
// speedup vs baseline: 1.1383x; 1.1383x over previous
#include <cuda_runtime.h>
#include <cuda_bf16.h>
#include <cstdint>

// Shapes (fixed for this problem)
#define N_TOTAL (64 * 4096)      // 262144 nodes
#define NHID    128
#define NN      4096             // nodes per graph == w3 dim
#define MB      64               // batch (graphs)

// table for s(f,g), t(f,g): range [-6,6]^2, h = 3/32, 129x129 points
#define TAB_N    129
#define TAB_LO   (-6.0f)
#define TAB_INVH (32.0f / 3.0f)

// ---------------- scratch (device globals; no allocation allowed) ----------
__device__ __align__(16) float2 g_fd [N_TOTAL];   // {agg1, deg} interleaved
__device__ __align__(16) float g_s   [N_TOTAL];
__device__ __align__(16) float g_t   [N_TOTAL];
__device__ __align__(16) float g_agg2[N_TOTAL];
#define GEMM_KSPLIT 8
__device__ float g_part[GEMM_KSPLIT * N_TOTAL];        // split-K partials (8MB)
__device__ __align__(16) unsigned short g_Ah[N_TOTAL]; // A bf16 hi
__device__ __align__(16) unsigned short g_Al[N_TOTAL]; // A bf16 lo
__device__ __align__(16) float2 g_tab[TAB_N * TAB_N];  // {s,t} table (133KB)

#define C_2LOG2E 2.88539008177792681f   // 2*log2(e)

__device__ __forceinline__ float ex2f(float x) {
    float e; asm("ex2.approx.f32 %0, %1;" : "=f"(e) : "f"(x)); return e;
}
__device__ __forceinline__ float rcpf(float x) {
    float r; asm("rcp.approx.f32 %0, %1;" : "=f"(r) : "f"(x)); return r;
}
// tanh from prescaled xp = 2*log2e*x : tanh = 1 - 2/(exp2(xp)+1)
__device__ __forceinline__ float tanh_exp2(float xp) {
    return fmaf(-2.0f, rcpf(ex2f(xp) + 1.0f), 1.0f);
}

// fast hi/lo bf16 split of two floats: hi = truncation (PRMT pack),
// lo = exact residual rounded to bf16 (packed cvt). 6 ops / 2 floats.
__device__ __forceinline__ void split2_fast(float a, float b,
                                            uint32_t& hi, uint32_t& lo) {
    uint32_t ua = __float_as_uint(a), ub = __float_as_uint(b);
    hi = __byte_perm(ua, ub, 0x7632);                   // {a_hi16, b_hi16}
    float ah = __uint_as_float(ua & 0xFFFF0000u);
    float bh = __uint_as_float(ub & 0xFFFF0000u);
    float la = a - ah, lb = b - bh;
    asm("cvt.rn.satfinite.bf16x2.f32 %0, %1, %2;" : "=r"(lo) : "f"(lb), "f"(la));
}

// ---------------- side-branch: build s/t table (footprint-light) ------------
__global__ void k_tab(const float* __restrict__ ws1, const float* __restrict__ wn1,
                      const float* __restrict__ b1,
                      const float* __restrict__ ws2, const float* __restrict__ wn2) {
    int p = blockIdx.x * blockDim.x + threadIdx.x;
    if (p >= TAB_N * TAB_N) return;
    int fi = p % TAB_N, gi = p / TAB_N;
    float f = TAB_LO + fi * (1.0f / TAB_INVH);
    float g = TAB_LO + gi * (1.0f / TAB_INVH);
    float s = 0.0f, t = 0.0f;
#pragma unroll 4
    for (int j = 0; j < NHID; j++) {
        float xp = C_2LOG2E * fmaf(f, __ldg(&ws1[j]),
                                   fmaf(g, __ldg(&wn1[j]), __ldg(&b1[j])));
        float r = tanh_exp2(xp);
        s = fmaf(r, __ldg(&ws2[j]), s);
        t = fmaf(r, __ldg(&wn2[j]), t);
    }
    g_tab[p] = make_float2(s, t);
}

// ---------------- kernel 0: zero scratch (vectorized) -----------------------
__global__ void k_zero(int n4) {   // n4 = N_TOTAL/4
    int i = blockIdx.x * blockDim.x + threadIdx.x;
    if (i < n4) {
        float4 z = make_float4(0.f, 0.f, 0.f, 0.f);
        reinterpret_cast<float4*>(g_fd)[2 * i]     = z;
        reinterpret_cast<float4*>(g_fd)[2 * i + 1] = z;
        reinterpret_cast<float4*>(g_agg2)[i]       = z;
    }
}

// ---------------- kernel 1: edge scatter pass 1 ({agg1,deg} v2 red) ---------
__global__ void k_edge1(const float* __restrict__ feat,
                        const int* __restrict__ src,
                        const int* __restrict__ dst, int E) {
    int e = blockIdx.x * blockDim.x + threadIdx.x;
    if (e < E) {
        int s = src[e];
        int d = dst[e];
        float v = __ldg(&feat[s]);
        asm volatile("red.global.add.v2.f32 [%0], {%1, %2};"
                     :: "l"(g_fd + d), "f"(v), "f"(1.0f) : "memory");
    }
}

// ---------------- kernel 2: s,t via bicubic table lookup (R6 proven) --------
__device__ __forceinline__ void cubic_w(float x, float w[4]) {
    float xm1 = x - 1.0f, xm2 = x - 2.0f, xp1 = x + 1.0f;
    float a = xm1 * xm2;
    float b = xp1 * x;
    w[0] = -x * a * (1.0f / 6.0f);
    w[1] = xp1 * a * 0.5f;
    w[2] = -b * xm2 * 0.5f;
    w[3] = b * xm1 * (1.0f / 6.0f);
}

__global__ __launch_bounds__(256) void k_node1(const float* __restrict__ feat,
                                               int n_total) {
    int n = blockIdx.x * blockDim.x + threadIdx.x;
    if (n >= n_total) return;

    float f   = feat[n];
    float2 fd = g_fd[n];
    float g   = __fdividef(fd.x, fmaxf(fd.y, 1.0f));

    float u = fminf(fmaxf((f - TAB_LO) * TAB_INVH, 1.0f), (float)(TAB_N - 3) - 1e-3f);
    float v = fminf(fmaxf((g - TAB_LO) * TAB_INVH, 1.0f), (float)(TAB_N - 3) - 1e-3f);
    int iu = (int)u;  float x = u - iu;
    int iv = (int)v;  float y = v - iv;

    float wx[4], wy[4];
    cubic_w(x, wx);
    cubic_w(y, wy);

    const float2* base = g_tab + (iv - 1) * TAB_N + (iu - 1);
    float s = 0.0f, t = 0.0f;
#pragma unroll
    for (int a = 0; a < 4; a++) {
        const float2* row = base + a * TAB_N;
        float rs = 0.0f, rt = 0.0f;
#pragma unroll
        for (int b = 0; b < 4; b++) {
            float2 tv = __ldg(&row[b]);
            rs = fmaf(wx[b], tv.x, rs);
            rt = fmaf(wx[b], tv.y, rt);
        }
        s = fmaf(wy[a], rs, s);
        t = fmaf(wy[a], rt, t);
    }
    g_s[n] = s;
    g_t[n] = t;
}

// ---------------- kernel 3: edge scatter pass 2 (agg2 of t) -----------------
__global__ void k_edge2(const int* __restrict__ src,
                        const int* __restrict__ dst, int E) {
    int e = blockIdx.x * blockDim.x + threadIdx.x;
    if (e < E) {
        atomicAdd(&g_agg2[dst[e]], __ldg(&g_t[src[e]]));
    }
}

// ---------------- kernel 4: out1; A = split(tanh(out1)) ---------------------
__global__ void k_node2(const float* __restrict__ b2,
                        float* __restrict__ out, int n_total) {
    int n = blockIdx.x * blockDim.x + threadIdx.x;
    if (n < n_total) {
        float o = g_s[n] + __fdividef(g_agg2[n], fmaxf(g_fd[n].y, 1.0f)) + b2[0];
        out[n] = o;                          // output1
        float h = tanh_exp2(C_2LOG2E * o);
        __nv_bfloat16 hh = __float2bfloat16_rn(h);
        float lo = h - __bfloat162float(hh);
        __nv_bfloat16 hl = __float2bfloat16_rn(lo);
        g_Ah[n] = *reinterpret_cast<unsigned short*>(&hh);
        g_Al[n] = *reinterpret_cast<unsigned short*>(&hl);
    }
}

// ---------------- kernel 5: GEMM partials = h2 @ w3 (bf16 3-pass split) -----
// R6 config (KSPLIT=8, BN=128, 256 blocks). Depth-2 register prefetch with
// STATIC slots: main loop "#pragma unroll 2" makes sl=ck&1 compile-time, so
// staging arrays stay in registers (the R9/R10 regression was these arrays
// demoted to local memory under dynamic indexing). launch_bounds(256,2)
// pins 2 blocks/SM. Non-atomic partial stores.
#define GEMM_BN 128
#define GEMM_KRANGE (NN / GEMM_KSPLIT)   // 512
#define GEMM_NCHUNK (GEMM_KRANGE / 16)   // 32

__device__ __forceinline__ void mma_bf16(float c[4], const uint32_t a[4],
                                         const uint32_t b[2]) {
    asm volatile(
        "mma.sync.aligned.m16n8k16.row.col.f32.bf16.bf16.f32 "
        "{%0,%1,%2,%3}, {%4,%5,%6,%7}, {%8,%9}, {%0,%1,%2,%3};\n"
        : "+f"(c[0]), "+f"(c[1]), "+f"(c[2]), "+f"(c[3])
        : "r"(a[0]), "r"(a[1]), "r"(a[2]), "r"(a[3]), "r"(b[0]), "r"(b[1]));
}
__device__ __forceinline__ void ldsm_x4(uint32_t r[4], uint32_t addr) {
    asm volatile("ldmatrix.sync.aligned.m8n8.x4.shared.b16 {%0,%1,%2,%3}, [%4];"
                 : "=r"(r[0]), "=r"(r[1]), "=r"(r[2]), "=r"(r[3]) : "r"(addr));
}
__device__ __forceinline__ void ldsm_x2t(uint32_t r[2], uint32_t addr) {
    asm volatile("ldmatrix.sync.aligned.m8n8.x2.trans.shared.b16 {%0,%1}, [%2];"
                 : "=r"(r[0]), "=r"(r[1]) : "r"(addr));
}

__global__ __launch_bounds__(256, 2) void k_gemm(const float* __restrict__ w3) {
    __shared__ __align__(16) unsigned short sAh[2][MB][16], sAl[2][MB][16];
    __shared__ __align__(16) unsigned short sBh[2][16][GEMM_BN], sBl[2][16][GEMM_BN];

    int tid  = threadIdx.x;
    int warp = tid >> 5;
    int lane = tid & 31;
    int g    = lane >> 2;
    int tg   = lane & 3;
    int n0   = blockIdx.x * GEMM_BN;
    int kb   = blockIdx.y * GEMM_KRANGE;

    int rA = tid >> 2;              // 0..63
    int cA = (tid & 3) * 4;         // ushort col in A tile
    int rB = tid >> 5;              // 0..7 (and +8)
    int cB = (tid & 31) * 4;        // float col in B tile

    const unsigned short* pAh = &g_Ah[rA * NN + cA];
    const unsigned short* pAl = &g_Al[rA * NN + cA];
    const float* pB0 = &w3[(size_t)rB * NN + n0 + cB];
    const float* pB1 = &w3[(size_t)(rB + 8) * NN + n0 + cB];

    float acc[4][2][4];
#pragma unroll
    for (int mi = 0; mi < 4; mi++)
#pragma unroll
        for (int ni = 0; ni < 2; ni++)
#pragma unroll
            for (int r = 0; r < 4; r++) acc[mi][ni][r] = 0.0f;

    // depth-2 register prefetch (static slots via unroll-2 below)
    uint2 rah[2], ral[2]; float4 rb0[2], rb1[2];
#pragma unroll
    for (int sl = 0; sl < 2; sl++) {
        int k0 = kb + sl * 16;
        rah[sl] = *reinterpret_cast<const uint2*>(pAh + k0);
        ral[sl] = *reinterpret_cast<const uint2*>(pAl + k0);
        rb0[sl] = *reinterpret_cast<const float4*>(pB0 + (size_t)k0 * NN);
        rb1[sl] = *reinterpret_cast<const float4*>(pB1 + (size_t)k0 * NN);
    }

    uint32_t aAh = (uint32_t)__cvta_generic_to_shared(
        &sAh[0][(lane & 15)][(lane >> 4) * 8]);
    uint32_t aAl = (uint32_t)__cvta_generic_to_shared(
        &sAl[0][(lane & 15)][(lane >> 4) * 8]);
    uint32_t aBh = (uint32_t)__cvta_generic_to_shared(
        &sBh[0][(lane & 15)][warp * 16]);
    uint32_t aBl = (uint32_t)__cvta_generic_to_shared(
        &sBl[0][(lane & 15)][warp * 16]);
    const uint32_t strideAbuf = MB * 16 * 2;
    const uint32_t strideBbuf = 16 * GEMM_BN * 2;

#pragma unroll 2
    for (int ck = 0; ck < GEMM_NCHUNK; ck++) {
        const int sl = ck & 1;   // compile-time inside each unrolled copy
        {
            *reinterpret_cast<uint2*>(&sAh[sl][rA][cA]) = rah[sl];
            *reinterpret_cast<uint2*>(&sAl[sl][rA][cA]) = ral[sl];
            uint32_t h0, l0, h1, l1;
            split2_fast(rb0[sl].x, rb0[sl].y, h0, l0);
            split2_fast(rb0[sl].z, rb0[sl].w, h1, l1);
            *reinterpret_cast<uint2*>(&sBh[sl][rB][cB]) = make_uint2(h0, h1);
            *reinterpret_cast<uint2*>(&sBl[sl][rB][cB]) = make_uint2(l0, l1);
            split2_fast(rb1[sl].x, rb1[sl].y, h0, l0);
            split2_fast(rb1[sl].z, rb1[sl].w, h1, l1);
            *reinterpret_cast<uint2*>(&sBh[sl][rB + 8][cB]) = make_uint2(h0, h1);
            *reinterpret_cast<uint2*>(&sBl[sl][rB + 8][cB]) = make_uint2(l0, l1);
        }
        if (ck + 2 < GEMM_NCHUNK) {
            int k0 = kb + (ck + 2) * 16;
            rah[sl] = *reinterpret_cast<const uint2*>(pAh + k0);
            ral[sl] = *reinterpret_cast<const uint2*>(pAl + k0);
            rb0[sl] = *reinterpret_cast<const float4*>(pB0 + (size_t)k0 * NN);
            rb1[sl] = *reinterpret_cast<const float4*>(pB1 + (size_t)k0 * NN);
        }
        __syncthreads();

        uint32_t aH[4][4], aL[4][4];
#pragma unroll
        for (int mi = 0; mi < 4; mi++) {
            ldsm_x4(aH[mi], aAh + sl * strideAbuf + mi * 16 * 16 * 2);
            ldsm_x4(aL[mi], aAl + sl * strideAbuf + mi * 16 * 16 * 2);
        }
        uint32_t bH[2][2], bL[2][2];
#pragma unroll
        for (int ni = 0; ni < 2; ni++) {
            ldsm_x2t(bH[ni], aBh + sl * strideBbuf + ni * 8 * 2);
            ldsm_x2t(bL[ni], aBl + sl * strideBbuf + ni * 8 * 2);
        }
#pragma unroll
        for (int mi = 0; mi < 4; mi++)
#pragma unroll
            for (int ni = 0; ni < 2; ni++) {
                mma_bf16(acc[mi][ni], aH[mi], bH[ni]);
                mma_bf16(acc[mi][ni], aH[mi], bL[ni]);
                mma_bf16(acc[mi][ni], aL[mi], bH[ni]);
            }
    }

    float* part = g_part + (size_t)blockIdx.y * N_TOTAL;
#pragma unroll
    for (int mi = 0; mi < 4; mi++) {
        int row = mi * 16 + g;
#pragma unroll
        for (int ni = 0; ni < 2; ni++) {
            int col = n0 + warp * 16 + ni * 8 + 2 * tg;
            *reinterpret_cast<float2*>(&part[(size_t)row * NN + col]) =
                make_float2(acc[mi][ni][0], acc[mi][ni][1]);
            *reinterpret_cast<float2*>(&part[(size_t)(row + 8) * NN + col]) =
                make_float2(acc[mi][ni][2], acc[mi][ni][3]);
        }
    }
}

// ---------------- kernel 6: reduce split-K partials + b3 --------------------
__global__ void k_red(const float* __restrict__ b3,
                      float* __restrict__ out2, int n4) {  // n4 = N_TOTAL/4
    int i = blockIdx.x * blockDim.x + threadIdx.x;
    if (i < n4) {
        float4 a = reinterpret_cast<const float4*>(b3)[i & (NN / 4 - 1)];
#pragma unroll
        for (int j = 0; j < GEMM_KSPLIT; j++) {
            float4 pv = reinterpret_cast<const float4*>(g_part)[(size_t)j * (N_TOTAL / 4) + i];
            a.x += pv.x; a.y += pv.y; a.z += pv.z; a.w += pv.w;
        }
        reinterpret_cast<float4*>(out2)[i] = a;
    }
}

// ---------------- launch ----------------------------------------------------
extern "C" void kernel_launch(void* const* d_in, const int* in_sizes, int n_in,
                              void* d_out, int out_size) {
    const float* feat = (const float*)d_in[0];
    const int*   src  = (const int*)d_in[1];
    const int*   dst  = (const int*)d_in[2];
    const float* ws1  = (const float*)d_in[3];
    const float* wn1  = (const float*)d_in[4];
    const float* b1   = (const float*)d_in[5];
    const float* ws2  = (const float*)d_in[6];
    const float* wn2  = (const float*)d_in[7];
    const float* b2   = (const float*)d_in[8];
    const float* w3   = (const float*)d_in[9];
    const float* b3   = (const float*)d_in[10];
    float* out = (float*)d_out;

    int N = in_sizes[0];   // 262144
    int E = in_sizes[1];   // 2097152

    // side stream: table build only (tiny; overlapped with zero+edge1)
    cudaStream_t s2;
    cudaStreamCreateWithFlags(&s2, cudaStreamNonBlocking);
    cudaEvent_t eF, eJ;
    cudaEventCreateWithFlags(&eF, cudaEventDisableTiming);
    cudaEventCreateWithFlags(&eJ, cudaEventDisableTiming);

    cudaEventRecord(eF, 0);
    cudaStreamWaitEvent(s2, eF, 0);
    k_tab<<<(TAB_N * TAB_N + 255) / 256, 256, 0, s2>>>(ws1, wn1, b1, ws2, wn2);
    cudaEventRecord(eJ, s2);

    k_zero<<<(N / 4 + 255) / 256, 256>>>(N / 4);
    k_edge1<<<(E + 255) / 256, 256>>>(feat, src, dst, E);

    cudaStreamWaitEvent(0, eJ, 0);
    k_node1<<<(N + 255) / 256, 256>>>(feat, N);
    k_edge2<<<(E + 255) / 256, 256>>>(src, dst, E);
    k_node2<<<(N + 255) / 256, 256>>>(b2, out, N);

    dim3 grid(NN / GEMM_BN, GEMM_KSPLIT);
    k_gemm<<<grid, 256>>>(w3);
    k_red<<<(N / 4 + 255) / 256, 256>>>(b3, out + N, N / 4);
}

// round 13
// speedup vs baseline: 1.3485x; 1.1847x over previous
#include <cuda_runtime.h>
#include <cuda_fp16.h>
#include <cstdint>

// Shapes (fixed for this problem)
#define N_TOTAL (64 * 4096)      // 262144 nodes
#define NHID    128
#define NN      4096             // nodes per graph == w3 dim
#define MB      64               // batch (graphs)

// table for s(f,g), t(f,g): range [-6,6]^2, h = 3/32, 129x129 points
#define TAB_N    129
#define TAB_LO   (-6.0f)
#define TAB_INVH (32.0f / 3.0f)

// ---------------- scratch (device globals; no allocation allowed) ----------
__device__ __align__(16) float2 g_fd [N_TOTAL];   // {agg1, deg} interleaved
__device__ __align__(16) float g_s   [N_TOTAL];
__device__ __align__(16) float g_t   [N_TOTAL];
__device__ __align__(16) float g_agg2[N_TOTAL];
#define GEMM_KSPLIT 8
__device__ float g_part[GEMM_KSPLIT * N_TOTAL];        // split-K partials (8MB)
__device__ __align__(16) unsigned short g_Ah[N_TOTAL]; // A fp16 hi
__device__ __align__(16) unsigned short g_Al[N_TOTAL]; // A fp16 lo (residual)
__device__ __align__(16) float2 g_tab[TAB_N * TAB_N];  // {s,t} table (133KB)

#define C_2LOG2E 2.88539008177792681f   // 2*log2(e)

__device__ __forceinline__ float ex2f(float x) {
    float e; asm("ex2.approx.f32 %0, %1;" : "=f"(e) : "f"(x)); return e;
}
__device__ __forceinline__ float rcpf(float x) {
    float r; asm("rcp.approx.f32 %0, %1;" : "=f"(r) : "f"(x)); return r;
}
// tanh from prescaled xp = 2*log2e*x : tanh = 1 - 2/(exp2(xp)+1)
__device__ __forceinline__ float tanh_exp2(float xp) {
    return fmaf(-2.0f, rcpf(ex2f(xp) + 1.0f), 1.0f);
}

// pack two floats into one f16x2 register: {lo=a, hi=b}
__device__ __forceinline__ uint32_t pack_f16x2(float a, float b) {
    uint32_t d;
    asm("cvt.rn.f16x2.f32 %0, %1, %2;" : "=r"(d) : "f"(b), "f"(a));
    return d;
}

// ---------------- side-branch: build s/t table (footprint-light) ------------
__global__ void k_tab(const float* __restrict__ ws1, const float* __restrict__ wn1,
                      const float* __restrict__ b1,
                      const float* __restrict__ ws2, const float* __restrict__ wn2) {
    int p = blockIdx.x * blockDim.x + threadIdx.x;
    if (p >= TAB_N * TAB_N) return;
    int fi = p % TAB_N, gi = p / TAB_N;
    float f = TAB_LO + fi * (1.0f / TAB_INVH);
    float g = TAB_LO + gi * (1.0f / TAB_INVH);
    float s = 0.0f, t = 0.0f;
#pragma unroll 4
    for (int j = 0; j < NHID; j++) {
        float xp = C_2LOG2E * fmaf(f, __ldg(&ws1[j]),
                                   fmaf(g, __ldg(&wn1[j]), __ldg(&b1[j])));
        float r = tanh_exp2(xp);
        s = fmaf(r, __ldg(&ws2[j]), s);
        t = fmaf(r, __ldg(&wn2[j]), t);
    }
    g_tab[p] = make_float2(s, t);
}

// ---------------- kernel 0: zero scratch (vectorized) -----------------------
__global__ void k_zero(int n4) {   // n4 = N_TOTAL/4
    int i = blockIdx.x * blockDim.x + threadIdx.x;
    if (i < n4) {
        float4 z = make_float4(0.f, 0.f, 0.f, 0.f);
        reinterpret_cast<float4*>(g_fd)[2 * i]     = z;
        reinterpret_cast<float4*>(g_fd)[2 * i + 1] = z;
        reinterpret_cast<float4*>(g_agg2)[i]       = z;
    }
}

// ---------------- kernel 1: edge scatter pass 1 ({agg1,deg} v2 red) ---------
__global__ void k_edge1(const float* __restrict__ feat,
                        const int* __restrict__ src,
                        const int* __restrict__ dst, int E) {
    int e = blockIdx.x * blockDim.x + threadIdx.x;
    if (e < E) {
        int s = src[e];
        int d = dst[e];
        float v = __ldg(&feat[s]);
        asm volatile("red.global.add.v2.f32 [%0], {%1, %2};"
                     :: "l"(g_fd + d), "f"(v), "f"(1.0f) : "memory");
    }
}

// ---------------- kernel 2: s,t via bicubic table lookup (R6 proven) --------
__device__ __forceinline__ void cubic_w(float x, float w[4]) {
    float xm1 = x - 1.0f, xm2 = x - 2.0f, xp1 = x + 1.0f;
    float a = xm1 * xm2;
    float b = xp1 * x;
    w[0] = -x * a * (1.0f / 6.0f);
    w[1] = xp1 * a * 0.5f;
    w[2] = -b * xm2 * 0.5f;
    w[3] = b * xm1 * (1.0f / 6.0f);
}

__global__ __launch_bounds__(256) void k_node1(const float* __restrict__ feat,
                                               int n_total) {
    int n = blockIdx.x * blockDim.x + threadIdx.x;
    if (n >= n_total) return;

    float f   = feat[n];
    float2 fd = g_fd[n];
    float g   = __fdividef(fd.x, fmaxf(fd.y, 1.0f));

    float u = fminf(fmaxf((f - TAB_LO) * TAB_INVH, 1.0f), (float)(TAB_N - 3) - 1e-3f);
    float v = fminf(fmaxf((g - TAB_LO) * TAB_INVH, 1.0f), (float)(TAB_N - 3) - 1e-3f);
    int iu = (int)u;  float x = u - iu;
    int iv = (int)v;  float y = v - iv;

    float wx[4], wy[4];
    cubic_w(x, wx);
    cubic_w(y, wy);

    const float2* base = g_tab + (iv - 1) * TAB_N + (iu - 1);
    float s = 0.0f, t = 0.0f;
#pragma unroll
    for (int a = 0; a < 4; a++) {
        const float2* row = base + a * TAB_N;
        float rs = 0.0f, rt = 0.0f;
#pragma unroll
        for (int b = 0; b < 4; b++) {
            float2 tv = __ldg(&row[b]);
            rs = fmaf(wx[b], tv.x, rs);
            rt = fmaf(wx[b], tv.y, rt);
        }
        s = fmaf(wy[a], rs, s);
        t = fmaf(wy[a], rt, t);
    }
    g_s[n] = s;
    g_t[n] = t;
}

// ---------------- kernel 3: edge scatter pass 2 (agg2 of t) -----------------
__global__ void k_edge2(const int* __restrict__ src,
                        const int* __restrict__ dst, int E) {
    int e = blockIdx.x * blockDim.x + threadIdx.x;
    if (e < E) {
        atomicAdd(&g_agg2[dst[e]], __ldg(&g_t[src[e]]));
    }
}

// ---------------- kernel 4: out1; A = fp16 hi/lo split of tanh(out1) --------
__global__ void k_node2(const float* __restrict__ b2,
                        float* __restrict__ out, int n_total) {
    int n = blockIdx.x * blockDim.x + threadIdx.x;
    if (n < n_total) {
        float o = g_s[n] + __fdividef(g_agg2[n], fmaxf(g_fd[n].y, 1.0f)) + b2[0];
        out[n] = o;                          // output1
        float h = tanh_exp2(C_2LOG2E * o);
        __half hh = __float2half_rn(h);
        float lo = h - __half2float(hh);
        __half hl = __float2half_rn(lo);
        g_Ah[n] = *reinterpret_cast<unsigned short*>(&hh);
        g_Al[n] = *reinterpret_cast<unsigned short*>(&hl);
    }
}

// ---------------- kernel 5: GEMM partials = h2 @ w3 (fp16 2-pass) -----------
// A = Ah + Al (exact fp16 split, preconverted); B = fp16(w3) inline.
// C = Ah*Bh + Al*Bh = A*fp16(B): error only from B rounding (~1.5e-4 rel,
// gate is 1e-3). 2 mma passes instead of 3 -> tensor floor 16us.
// R6-proven skeleton: KSPLIT=8, BN=128, depth-1 prefetch, 1 sync/iter.
#define GEMM_BN 128
#define GEMM_KRANGE (NN / GEMM_KSPLIT)   // 512
#define GEMM_NCHUNK (GEMM_KRANGE / 16)   // 32

__device__ __forceinline__ void mma_f16(float c[4], const uint32_t a[4],
                                        const uint32_t b[2]) {
    asm volatile(
        "mma.sync.aligned.m16n8k16.row.col.f32.f16.f16.f32 "
        "{%0,%1,%2,%3}, {%4,%5,%6,%7}, {%8,%9}, {%0,%1,%2,%3};\n"
        : "+f"(c[0]), "+f"(c[1]), "+f"(c[2]), "+f"(c[3])
        : "r"(a[0]), "r"(a[1]), "r"(a[2]), "r"(a[3]), "r"(b[0]), "r"(b[1]));
}
__device__ __forceinline__ void ldsm_x4(uint32_t r[4], uint32_t addr) {
    asm volatile("ldmatrix.sync.aligned.m8n8.x4.shared.b16 {%0,%1,%2,%3}, [%4];"
                 : "=r"(r[0]), "=r"(r[1]), "=r"(r[2]), "=r"(r[3]) : "r"(addr));
}
__device__ __forceinline__ void ldsm_x2t(uint32_t r[2], uint32_t addr) {
    asm volatile("ldmatrix.sync.aligned.m8n8.x2.trans.shared.b16 {%0,%1}, [%2];"
                 : "=r"(r[0]), "=r"(r[1]) : "r"(addr));
}

__global__ __launch_bounds__(256) void k_gemm(const float* __restrict__ w3) {
    __shared__ __align__(16) unsigned short sAh[2][MB][16], sAl[2][MB][16];
    __shared__ __align__(16) unsigned short sBh[2][16][GEMM_BN];

    int tid  = threadIdx.x;
    int warp = tid >> 5;
    int lane = tid & 31;
    int g    = lane >> 2;
    int tg   = lane & 3;
    int n0   = blockIdx.x * GEMM_BN;
    int kb   = blockIdx.y * GEMM_KRANGE;

    int rA = tid >> 2;              // 0..63
    int cA = (tid & 3) * 4;         // ushort col in A tile
    int rB = tid >> 5;              // 0..7 (and +8)
    int cB = (tid & 31) * 4;        // float col in B tile

    float acc[4][2][4];
#pragma unroll
    for (int mi = 0; mi < 4; mi++)
#pragma unroll
        for (int ni = 0; ni < 2; ni++)
#pragma unroll
            for (int r = 0; r < 4; r++) acc[mi][ni][r] = 0.0f;

    // prefetch chunk 0
    uint2 rah, ral; float4 rb0, rb1;
    {
        int k0 = kb;
        rah = *reinterpret_cast<const uint2*>(&g_Ah[rA * NN + k0 + cA]);
        ral = *reinterpret_cast<const uint2*>(&g_Al[rA * NN + k0 + cA]);
        rb0 = *reinterpret_cast<const float4*>(&w3[(size_t)(k0 + rB) * NN + n0 + cB]);
        rb1 = *reinterpret_cast<const float4*>(&w3[(size_t)(k0 + rB + 8) * NN + n0 + cB]);
    }

    uint32_t aAh = (uint32_t)__cvta_generic_to_shared(
        &sAh[0][(lane & 15)][(lane >> 4) * 8]);
    uint32_t aAl = (uint32_t)__cvta_generic_to_shared(
        &sAl[0][(lane & 15)][(lane >> 4) * 8]);
    uint32_t aBh = (uint32_t)__cvta_generic_to_shared(
        &sBh[0][(lane & 15)][warp * 16]);
    const uint32_t strideAbuf = MB * 16 * 2;
    const uint32_t strideBbuf = 16 * GEMM_BN * 2;

    int p = 0;
#pragma unroll 1
    for (int ck = 0; ck < GEMM_NCHUNK; ck++) {
        {
            *reinterpret_cast<uint2*>(&sAh[p][rA][cA]) = rah;
            *reinterpret_cast<uint2*>(&sAl[p][rA][cA]) = ral;
            *reinterpret_cast<uint2*>(&sBh[p][rB][cB]) =
                make_uint2(pack_f16x2(rb0.x, rb0.y), pack_f16x2(rb0.z, rb0.w));
            *reinterpret_cast<uint2*>(&sBh[p][rB + 8][cB]) =
                make_uint2(pack_f16x2(rb1.x, rb1.y), pack_f16x2(rb1.z, rb1.w));
        }
        if (ck + 1 < GEMM_NCHUNK) {
            int k0 = kb + (ck + 1) * 16;
            rah = *reinterpret_cast<const uint2*>(&g_Ah[rA * NN + k0 + cA]);
            ral = *reinterpret_cast<const uint2*>(&g_Al[rA * NN + k0 + cA]);
            rb0 = *reinterpret_cast<const float4*>(&w3[(size_t)(k0 + rB) * NN + n0 + cB]);
            rb1 = *reinterpret_cast<const float4*>(&w3[(size_t)(k0 + rB + 8) * NN + n0 + cB]);
        }
        __syncthreads();

        uint32_t aH[4][4], aL[4][4];
#pragma unroll
        for (int mi = 0; mi < 4; mi++) {
            ldsm_x4(aH[mi], aAh + p * strideAbuf + mi * 16 * 16 * 2);
            ldsm_x4(aL[mi], aAl + p * strideAbuf + mi * 16 * 16 * 2);
        }
        uint32_t bH[2][2];
#pragma unroll
        for (int ni = 0; ni < 2; ni++) {
            ldsm_x2t(bH[ni], aBh + p * strideBbuf + ni * 8 * 2);
        }
#pragma unroll
        for (int mi = 0; mi < 4; mi++)
#pragma unroll
            for (int ni = 0; ni < 2; ni++) {
                mma_f16(acc[mi][ni], aH[mi], bH[ni]);
                mma_f16(acc[mi][ni], aL[mi], bH[ni]);
            }
        p ^= 1;
    }

    // epilogue: plain v2 stores into this split's partial slab (no atomics)
    float* part = g_part + (size_t)blockIdx.y * N_TOTAL;
#pragma unroll
    for (int mi = 0; mi < 4; mi++) {
        int row = mi * 16 + g;
#pragma unroll
        for (int ni = 0; ni < 2; ni++) {
            int col = n0 + warp * 16 + ni * 8 + 2 * tg;
            *reinterpret_cast<float2*>(&part[(size_t)row * NN + col]) =
                make_float2(acc[mi][ni][0], acc[mi][ni][1]);
            *reinterpret_cast<float2*>(&part[(size_t)(row + 8) * NN + col]) =
                make_float2(acc[mi][ni][2], acc[mi][ni][3]);
        }
    }
}

// ---------------- kernel 6: reduce split-K partials + b3 --------------------
__global__ void k_red(const float* __restrict__ b3,
                      float* __restrict__ out2, int n4) {  // n4 = N_TOTAL/4
    int i = blockIdx.x * blockDim.x + threadIdx.x;
    if (i < n4) {
        float4 a = reinterpret_cast<const float4*>(b3)[i & (NN / 4 - 1)];
#pragma unroll
        for (int j = 0; j < GEMM_KSPLIT; j++) {
            float4 pv = reinterpret_cast<const float4*>(g_part)[(size_t)j * (N_TOTAL / 4) + i];
            a.x += pv.x; a.y += pv.y; a.z += pv.z; a.w += pv.w;
        }
        reinterpret_cast<float4*>(out2)[i] = a;
    }
}

// ---------------- launch ----------------------------------------------------
extern "C" void kernel_launch(void* const* d_in, const int* in_sizes, int n_in,
                              void* d_out, int out_size) {
    const float* feat = (const float*)d_in[0];
    const int*   src  = (const int*)d_in[1];
    const int*   dst  = (const int*)d_in[2];
    const float* ws1  = (const float*)d_in[3];
    const float* wn1  = (const float*)d_in[4];
    const float* b1   = (const float*)d_in[5];
    const float* ws2  = (const float*)d_in[6];
    const float* wn2  = (const float*)d_in[7];
    const float* b2   = (const float*)d_in[8];
    const float* w3   = (const float*)d_in[9];
    const float* b3   = (const float*)d_in[10];
    float* out = (float*)d_out;

    int N = in_sizes[0];   // 262144
    int E = in_sizes[1];   // 2097152

    // side stream: table build only (tiny; overlapped with zero+edge1)
    cudaStream_t s2;
    cudaStreamCreateWithFlags(&s2, cudaStreamNonBlocking);
    cudaEvent_t eF, eJ;
    cudaEventCreateWithFlags(&eF, cudaEventDisableTiming);
    cudaEventCreateWithFlags(&eJ, cudaEventDisableTiming);

    cudaEventRecord(eF, 0);
    cudaStreamWaitEvent(s2, eF, 0);
    k_tab<<<(TAB_N * TAB_N + 255) / 256, 256, 0, s2>>>(ws1, wn1, b1, ws2, wn2);
    cudaEventRecord(eJ, s2);

    k_zero<<<(N / 4 + 255) / 256, 256>>>(N / 4);
    k_edge1<<<(E + 255) / 256, 256>>>(feat, src, dst, E);

    cudaStreamWaitEvent(0, eJ, 0);
    k_node1<<<(N + 255) / 256, 256>>>(feat, N);
    k_edge2<<<(E + 255) / 256, 256>>>(src, dst, E);
    k_node2<<<(N + 255) / 256, 256>>>(b2, out, N);

    dim3 grid(NN / GEMM_BN, GEMM_KSPLIT);
    k_gemm<<<grid, 256>>>(w3);
    k_red<<<(N / 4 + 255) / 256, 256>>>(b3, out + N, N / 4);
}

// round 14
// speedup vs baseline: 1.3499x; 1.0010x over previous
#include <cuda_runtime.h>
#include <cuda_fp16.h>
#include <cstdint>

// Shapes (fixed for this problem)
#define N_TOTAL (64 * 4096)      // 262144 nodes
#define NHID    128
#define NN      4096             // nodes per graph == w3 dim
#define MB      64               // batch (graphs)

// table for s(f,g), t(f,g): range [-6,6]^2, h = 3/32, 129x129 points
#define TAB_N    129
#define TAB_LO   (-6.0f)
#define TAB_INVH (32.0f / 3.0f)

// ---------------- scratch (device globals; no allocation allowed) ----------
__device__ __align__(16) float2 g_fd [N_TOTAL];   // {agg1, deg} interleaved
__device__ __align__(16) float g_s   [N_TOTAL];
__device__ __align__(16) float g_t   [N_TOTAL];
__device__ __align__(16) float g_agg2[N_TOTAL];
#define GEMM_KSPLIT 8
__device__ float g_part[GEMM_KSPLIT * N_TOTAL];        // split-K partials (8MB)
__device__ __align__(16) unsigned short g_Ah[N_TOTAL]; // A = fp16(h2)
__device__ __align__(16) float2 g_tab[TAB_N * TAB_N];  // {s,t} table (133KB)

#define C_2LOG2E 2.88539008177792681f   // 2*log2(e)

__device__ __forceinline__ float ex2f(float x) {
    float e; asm("ex2.approx.f32 %0, %1;" : "=f"(e) : "f"(x)); return e;
}
__device__ __forceinline__ float rcpf(float x) {
    float r; asm("rcp.approx.f32 %0, %1;" : "=f"(r) : "f"(x)); return r;
}
// tanh from prescaled xp = 2*log2e*x : tanh = 1 - 2/(exp2(xp)+1)
__device__ __forceinline__ float tanh_exp2(float xp) {
    return fmaf(-2.0f, rcpf(ex2f(xp) + 1.0f), 1.0f);
}

// pack two floats into one f16x2 register: {lo=a, hi=b}
__device__ __forceinline__ uint32_t pack_f16x2(float a, float b) {
    uint32_t d;
    asm("cvt.rn.f16x2.f32 %0, %1, %2;" : "=r"(d) : "f"(b), "f"(a));
    return d;
}

// ---------------- side-branch: build s/t table (footprint-light) ------------
__global__ void k_tab(const float* __restrict__ ws1, const float* __restrict__ wn1,
                      const float* __restrict__ b1,
                      const float* __restrict__ ws2, const float* __restrict__ wn2) {
    int p = blockIdx.x * blockDim.x + threadIdx.x;
    if (p >= TAB_N * TAB_N) return;
    int fi = p % TAB_N, gi = p / TAB_N;
    float f = TAB_LO + fi * (1.0f / TAB_INVH);
    float g = TAB_LO + gi * (1.0f / TAB_INVH);
    float s = 0.0f, t = 0.0f;
#pragma unroll 4
    for (int j = 0; j < NHID; j++) {
        float xp = C_2LOG2E * fmaf(f, __ldg(&ws1[j]),
                                   fmaf(g, __ldg(&wn1[j]), __ldg(&b1[j])));
        float r = tanh_exp2(xp);
        s = fmaf(r, __ldg(&ws2[j]), s);
        t = fmaf(r, __ldg(&wn2[j]), t);
    }
    g_tab[p] = make_float2(s, t);
}

// ---------------- kernel 0: zero {agg1,deg} only (agg2 zeroed in node1) -----
__global__ void k_zero(int n4) {   // n4 = N_TOTAL/4
    int i = blockIdx.x * blockDim.x + threadIdx.x;
    if (i < n4) {
        float4 z = make_float4(0.f, 0.f, 0.f, 0.f);
        reinterpret_cast<float4*>(g_fd)[2 * i]     = z;
        reinterpret_cast<float4*>(g_fd)[2 * i + 1] = z;
    }
}

// ---------------- kernel 1: edge scatter pass 1 ({agg1,deg} v2 red) ---------
__global__ void k_edge1(const float* __restrict__ feat,
                        const int* __restrict__ src,
                        const int* __restrict__ dst, int E) {
    int e = blockIdx.x * blockDim.x + threadIdx.x;
    if (e < E) {
        int s = src[e];
        int d = dst[e];
        float v = __ldg(&feat[s]);
        asm volatile("red.global.add.v2.f32 [%0], {%1, %2};"
                     :: "l"(g_fd + d), "f"(v), "f"(1.0f) : "memory");
    }
}

// ---------------- kernel 2: s,t via bicubic table lookup; zero agg2 ---------
__device__ __forceinline__ void cubic_w(float x, float w[4]) {
    float xm1 = x - 1.0f, xm2 = x - 2.0f, xp1 = x + 1.0f;
    float a = xm1 * xm2;
    float b = xp1 * x;
    w[0] = -x * a * (1.0f / 6.0f);
    w[1] = xp1 * a * 0.5f;
    w[2] = -b * xm2 * 0.5f;
    w[3] = b * xm1 * (1.0f / 6.0f);
}

__global__ __launch_bounds__(256) void k_node1(const float* __restrict__ feat,
                                               int n_total) {
    int n = blockIdx.x * blockDim.x + threadIdx.x;
    if (n >= n_total) return;

    float f   = feat[n];
    float2 fd = g_fd[n];
    float g   = __fdividef(fd.x, fmaxf(fd.y, 1.0f));

    float u = fminf(fmaxf((f - TAB_LO) * TAB_INVH, 1.0f), (float)(TAB_N - 3) - 1e-3f);
    float v = fminf(fmaxf((g - TAB_LO) * TAB_INVH, 1.0f), (float)(TAB_N - 3) - 1e-3f);
    int iu = (int)u;  float x = u - iu;
    int iv = (int)v;  float y = v - iv;

    float wx[4], wy[4];
    cubic_w(x, wx);
    cubic_w(y, wy);

    const float2* base = g_tab + (iv - 1) * TAB_N + (iu - 1);
    float s = 0.0f, t = 0.0f;
#pragma unroll
    for (int a = 0; a < 4; a++) {
        const float2* row = base + a * TAB_N;
        float rs = 0.0f, rt = 0.0f;
#pragma unroll
        for (int b = 0; b < 4; b++) {
            float2 tv = __ldg(&row[b]);
            rs = fmaf(wx[b], tv.x, rs);
            rt = fmaf(wx[b], tv.y, rt);
        }
        s = fmaf(wy[a], rs, s);
        t = fmaf(wy[a], rt, t);
    }
    g_s[n] = s;
    g_t[n] = t;
    g_agg2[n] = 0.0f;   // zero for edge2 (runs after this kernel)
}

// ---------------- kernel 3: edge scatter pass 2 (agg2 of t) -----------------
__global__ void k_edge2(const int* __restrict__ src,
                        const int* __restrict__ dst, int E) {
    int e = blockIdx.x * blockDim.x + threadIdx.x;
    if (e < E) {
        atomicAdd(&g_agg2[dst[e]], __ldg(&g_t[src[e]]));
    }
}

// ---------------- kernel 4: out1; A = fp16(tanh(out1)) ----------------------
__global__ void k_node2(const float* __restrict__ b2,
                        float* __restrict__ out, int n_total) {
    int n = blockIdx.x * blockDim.x + threadIdx.x;
    if (n < n_total) {
        float o = g_s[n] + __fdividef(g_agg2[n], fmaxf(g_fd[n].y, 1.0f)) + b2[0];
        out[n] = o;                          // output1
        float h = tanh_exp2(C_2LOG2E * o);
        __half hh = __float2half_rn(h);
        g_Ah[n] = *reinterpret_cast<unsigned short*>(&hh);
    }
}

// ---------------- kernel 5: GEMM partials = h2 @ w3 (fp16 single pass) ------
// A = fp16(h2) preconverted, B = fp16(w3) inline. Error ~2.9e-4 rel
// (A and B rounding, gate 1e-3). DRAM-floor bound (~11us for w3).
// R6-proven skeleton: KSPLIT=8, BN=128, depth-1 prefetch, 1 sync/iter.
#define GEMM_BN 128
#define GEMM_KRANGE (NN / GEMM_KSPLIT)   // 512
#define GEMM_NCHUNK (GEMM_KRANGE / 16)   // 32

__device__ __forceinline__ void mma_f16(float c[4], const uint32_t a[4],
                                        const uint32_t b[2]) {
    asm volatile(
        "mma.sync.aligned.m16n8k16.row.col.f32.f16.f16.f32 "
        "{%0,%1,%2,%3}, {%4,%5,%6,%7}, {%8,%9}, {%0,%1,%2,%3};\n"
        : "+f"(c[0]), "+f"(c[1]), "+f"(c[2]), "+f"(c[3])
        : "r"(a[0]), "r"(a[1]), "r"(a[2]), "r"(a[3]), "r"(b[0]), "r"(b[1]));
}
__device__ __forceinline__ void ldsm_x4(uint32_t r[4], uint32_t addr) {
    asm volatile("ldmatrix.sync.aligned.m8n8.x4.shared.b16 {%0,%1,%2,%3}, [%4];"
                 : "=r"(r[0]), "=r"(r[1]), "=r"(r[2]), "=r"(r[3]) : "r"(addr));
}
__device__ __forceinline__ void ldsm_x2t(uint32_t r[2], uint32_t addr) {
    asm volatile("ldmatrix.sync.aligned.m8n8.x2.trans.shared.b16 {%0,%1}, [%2];"
                 : "=r"(r[0]), "=r"(r[1]) : "r"(addr));
}

__global__ __launch_bounds__(256) void k_gemm(const float* __restrict__ w3) {
    __shared__ __align__(16) unsigned short sAh[2][MB][16];
    __shared__ __align__(16) unsigned short sBh[2][16][GEMM_BN];

    int tid  = threadIdx.x;
    int warp = tid >> 5;
    int lane = tid & 31;
    int g    = lane >> 2;
    int tg   = lane & 3;
    int n0   = blockIdx.x * GEMM_BN;
    int kb   = blockIdx.y * GEMM_KRANGE;

    int rA = tid >> 2;              // 0..63
    int cA = (tid & 3) * 4;         // ushort col in A tile
    int rB = tid >> 5;              // 0..7 (and +8)
    int cB = (tid & 31) * 4;        // float col in B tile

    float acc[4][2][4];
#pragma unroll
    for (int mi = 0; mi < 4; mi++)
#pragma unroll
        for (int ni = 0; ni < 2; ni++)
#pragma unroll
            for (int r = 0; r < 4; r++) acc[mi][ni][r] = 0.0f;

    // prefetch chunk 0
    uint2 rah; float4 rb0, rb1;
    {
        int k0 = kb;
        rah = *reinterpret_cast<const uint2*>(&g_Ah[rA * NN + k0 + cA]);
        rb0 = *reinterpret_cast<const float4*>(&w3[(size_t)(k0 + rB) * NN + n0 + cB]);
        rb1 = *reinterpret_cast<const float4*>(&w3[(size_t)(k0 + rB + 8) * NN + n0 + cB]);
    }

    uint32_t aAh = (uint32_t)__cvta_generic_to_shared(
        &sAh[0][(lane & 15)][(lane >> 4) * 8]);
    uint32_t aBh = (uint32_t)__cvta_generic_to_shared(
        &sBh[0][(lane & 15)][warp * 16]);
    const uint32_t strideAbuf = MB * 16 * 2;
    const uint32_t strideBbuf = 16 * GEMM_BN * 2;

    int p = 0;
#pragma unroll 1
    for (int ck = 0; ck < GEMM_NCHUNK; ck++) {
        {
            *reinterpret_cast<uint2*>(&sAh[p][rA][cA]) = rah;
            *reinterpret_cast<uint2*>(&sBh[p][rB][cB]) =
                make_uint2(pack_f16x2(rb0.x, rb0.y), pack_f16x2(rb0.z, rb0.w));
            *reinterpret_cast<uint2*>(&sBh[p][rB + 8][cB]) =
                make_uint2(pack_f16x2(rb1.x, rb1.y), pack_f16x2(rb1.z, rb1.w));
        }
        if (ck + 1 < GEMM_NCHUNK) {
            int k0 = kb + (ck + 1) * 16;
            rah = *reinterpret_cast<const uint2*>(&g_Ah[rA * NN + k0 + cA]);
            rb0 = *reinterpret_cast<const float4*>(&w3[(size_t)(k0 + rB) * NN + n0 + cB]);
            rb1 = *reinterpret_cast<const float4*>(&w3[(size_t)(k0 + rB + 8) * NN + n0 + cB]);
        }
        __syncthreads();

        uint32_t aH[4][4];
#pragma unroll
        for (int mi = 0; mi < 4; mi++) {
            ldsm_x4(aH[mi], aAh + p * strideAbuf + mi * 16 * 16 * 2);
        }
        uint32_t bH[2][2];
#pragma unroll
        for (int ni = 0; ni < 2; ni++) {
            ldsm_x2t(bH[ni], aBh + p * strideBbuf + ni * 8 * 2);
        }
#pragma unroll
        for (int mi = 0; mi < 4; mi++)
#pragma unroll
            for (int ni = 0; ni < 2; ni++) {
                mma_f16(acc[mi][ni], aH[mi], bH[ni]);
            }
        p ^= 1;
    }

    // epilogue: plain v2 stores into this split's partial slab (no atomics)
    float* part = g_part + (size_t)blockIdx.y * N_TOTAL;
#pragma unroll
    for (int mi = 0; mi < 4; mi++) {
        int row = mi * 16 + g;
#pragma unroll
        for (int ni = 0; ni < 2; ni++) {
            int col = n0 + warp * 16 + ni * 8 + 2 * tg;
            *reinterpret_cast<float2*>(&part[(size_t)row * NN + col]) =
                make_float2(acc[mi][ni][0], acc[mi][ni][1]);
            *reinterpret_cast<float2*>(&part[(size_t)(row + 8) * NN + col]) =
                make_float2(acc[mi][ni][2], acc[mi][ni][3]);
        }
    }
}

// ---------------- kernel 6: reduce split-K partials + b3 --------------------
__global__ void k_red(const float* __restrict__ b3,
                      float* __restrict__ out2, int n4) {  // n4 = N_TOTAL/4
    int i = blockIdx.x * blockDim.x + threadIdx.x;
    if (i < n4) {
        float4 a = reinterpret_cast<const float4*>(b3)[i & (NN / 4 - 1)];
#pragma unroll
        for (int j = 0; j < GEMM_KSPLIT; j++) {
            float4 pv = reinterpret_cast<const float4*>(g_part)[(size_t)j * (N_TOTAL / 4) + i];
            a.x += pv.x; a.y += pv.y; a.z += pv.z; a.w += pv.w;
        }
        reinterpret_cast<float4*>(out2)[i] = a;
    }
}

// ---------------- launch ----------------------------------------------------
extern "C" void kernel_launch(void* const* d_in, const int* in_sizes, int n_in,
                              void* d_out, int out_size) {
    const float* feat = (const float*)d_in[0];
    const int*   src  = (const int*)d_in[1];
    const int*   dst  = (const int*)d_in[2];
    const float* ws1  = (const float*)d_in[3];
    const float* wn1  = (const float*)d_in[4];
    const float* b1   = (const float*)d_in[5];
    const float* ws2  = (const float*)d_in[6];
    const float* wn2  = (const float*)d_in[7];
    const float* b2   = (const float*)d_in[8];
    const float* w3   = (const float*)d_in[9];
    const float* b3   = (const float*)d_in[10];
    float* out = (float*)d_out;

    int N = in_sizes[0];   // 262144
    int E = in_sizes[1];   // 2097152

    // side stream: table build only (tiny; overlapped with zero+edge1)
    cudaStream_t s2;
    cudaStreamCreateWithFlags(&s2, cudaStreamNonBlocking);
    cudaEvent_t eF, eJ;
    cudaEventCreateWithFlags(&eF, cudaEventDisableTiming);
    cudaEventCreateWithFlags(&eJ, cudaEventDisableTiming);

    cudaEventRecord(eF, 0);
    cudaStreamWaitEvent(s2, eF, 0);
    k_tab<<<(TAB_N * TAB_N + 255) / 256, 256, 0, s2>>>(ws1, wn1, b1, ws2, wn2);
    cudaEventRecord(eJ, s2);

    k_zero<<<(N / 4 + 255) / 256, 256>>>(N / 4);
    k_edge1<<<(E + 255) / 256, 256>>>(feat, src, dst, E);

    cudaStreamWaitEvent(0, eJ, 0);
    k_node1<<<(N + 255) / 256, 256>>>(feat, N);
    k_edge2<<<(E + 255) / 256, 256>>>(src, dst, E);
    k_node2<<<(N + 255) / 256, 256>>>(b2, out, N);

    dim3 grid(NN / GEMM_BN, GEMM_KSPLIT);
    k_gemm<<<grid, 256>>>(w3);
    k_red<<<(N / 4 + 255) / 256, 256>>>(b3, out + N, N / 4);
}

// round 15
// speedup vs baseline: 1.4435x; 1.0693x over previous
#include <cuda_runtime.h>
#include <cuda_fp16.h>
#include <cstdint>

// Shapes (fixed for this problem)
#define N_TOTAL (64 * 4096)      // 262144 nodes
#define NHID    128
#define NN      4096             // nodes per graph == w3 dim
#define MB      64               // batch (graphs)

// table for s(f,g), t(f,g): range [-6,6]^2, h = 3/32, 129x129 points
#define TAB_N    129
#define TAB_LO   (-6.0f)
#define TAB_INVH (32.0f / 3.0f)

// ---------------- scratch (device globals; no allocation allowed) ----------
__device__ __align__(16) float2 g_fd [N_TOTAL];   // {agg1, deg} interleaved
__device__ __align__(16) float g_s   [N_TOTAL];
__device__ __align__(16) float g_t   [N_TOTAL];
__device__ __align__(16) float g_agg2[N_TOTAL];
#define GEMM_KSPLIT 8
__device__ float g_part[GEMM_KSPLIT * N_TOTAL];        // split-K partials (8MB)
__device__ __align__(16) unsigned short g_Ah[N_TOTAL]; // A = fp16(h2)
__device__ __align__(16) float2 g_tab[TAB_N * TAB_N];  // {s,t} table (133KB)

#define C_2LOG2E 2.88539008177792681f   // 2*log2(e)

__device__ __forceinline__ float ex2f(float x) {
    float e; asm("ex2.approx.f32 %0, %1;" : "=f"(e) : "f"(x)); return e;
}
__device__ __forceinline__ float rcpf(float x) {
    float r; asm("rcp.approx.f32 %0, %1;" : "=f"(r) : "f"(x)); return r;
}
// tanh from prescaled xp = 2*log2e*x : tanh = 1 - 2/(exp2(xp)+1)
__device__ __forceinline__ float tanh_exp2(float xp) {
    return fmaf(-2.0f, rcpf(ex2f(xp) + 1.0f), 1.0f);
}

// pack two floats into one f16x2 register: {lo=a, hi=b}
__device__ __forceinline__ uint32_t pack_f16x2(float a, float b) {
    uint32_t d;
    asm("cvt.rn.f16x2.f32 %0, %1, %2;" : "=r"(d) : "f"(b), "f"(a));
    return d;
}

// ---------------- side-branch: build s/t table (footprint-light) ------------
__global__ void k_tab(const float* __restrict__ ws1, const float* __restrict__ wn1,
                      const float* __restrict__ b1,
                      const float* __restrict__ ws2, const float* __restrict__ wn2) {
    int p = blockIdx.x * blockDim.x + threadIdx.x;
    if (p >= TAB_N * TAB_N) return;
    int fi = p % TAB_N, gi = p / TAB_N;
    float f = TAB_LO + fi * (1.0f / TAB_INVH);
    float g = TAB_LO + gi * (1.0f / TAB_INVH);
    float s = 0.0f, t = 0.0f;
#pragma unroll 4
    for (int j = 0; j < NHID; j++) {
        float xp = C_2LOG2E * fmaf(f, __ldg(&ws1[j]),
                                   fmaf(g, __ldg(&wn1[j]), __ldg(&b1[j])));
        float r = tanh_exp2(xp);
        s = fmaf(r, __ldg(&ws2[j]), s);
        t = fmaf(r, __ldg(&wn2[j]), t);
    }
    g_tab[p] = make_float2(s, t);
}

// ---------------- kernel 0: zero {agg1,deg} only (agg2 zeroed in node1) -----
__global__ void k_zero(int n4) {   // n4 = N_TOTAL/4
    int i = blockIdx.x * blockDim.x + threadIdx.x;
    if (i < n4) {
        float4 z = make_float4(0.f, 0.f, 0.f, 0.f);
        reinterpret_cast<float4*>(g_fd)[2 * i]     = z;
        reinterpret_cast<float4*>(g_fd)[2 * i + 1] = z;
    }
}

// ---------------- kernel 1: edge scatter pass 1 ({agg1,deg} v2 red) ---------
__global__ void k_edge1(const float* __restrict__ feat,
                        const int* __restrict__ src,
                        const int* __restrict__ dst, int E) {
    int e = blockIdx.x * blockDim.x + threadIdx.x;
    if (e < E) {
        int s = src[e];
        int d = dst[e];
        float v = __ldg(&feat[s]);
        asm volatile("red.global.add.v2.f32 [%0], {%1, %2};"
                     :: "l"(g_fd + d), "f"(v), "f"(1.0f) : "memory");
    }
}

// ---------------- kernel 2: s,t via bicubic table lookup; zero agg2 ---------
__device__ __forceinline__ void cubic_w(float x, float w[4]) {
    float xm1 = x - 1.0f, xm2 = x - 2.0f, xp1 = x + 1.0f;
    float a = xm1 * xm2;
    float b = xp1 * x;
    w[0] = -x * a * (1.0f / 6.0f);
    w[1] = xp1 * a * 0.5f;
    w[2] = -b * xm2 * 0.5f;
    w[3] = b * xm1 * (1.0f / 6.0f);
}

__global__ __launch_bounds__(256) void k_node1(const float* __restrict__ feat,
                                               int n_total) {
    int n = blockIdx.x * blockDim.x + threadIdx.x;
    if (n >= n_total) return;

    float f   = feat[n];
    float2 fd = g_fd[n];
    float g   = __fdividef(fd.x, fmaxf(fd.y, 1.0f));

    float u = fminf(fmaxf((f - TAB_LO) * TAB_INVH, 1.0f), (float)(TAB_N - 3) - 1e-3f);
    float v = fminf(fmaxf((g - TAB_LO) * TAB_INVH, 1.0f), (float)(TAB_N - 3) - 1e-3f);
    int iu = (int)u;  float x = u - iu;
    int iv = (int)v;  float y = v - iv;

    float wx[4], wy[4];
    cubic_w(x, wx);
    cubic_w(y, wy);

    const float2* base = g_tab + (iv - 1) * TAB_N + (iu - 1);
    float s = 0.0f, t = 0.0f;
#pragma unroll
    for (int a = 0; a < 4; a++) {
        const float2* row = base + a * TAB_N;
        float rs = 0.0f, rt = 0.0f;
#pragma unroll
        for (int b = 0; b < 4; b++) {
            float2 tv = __ldg(&row[b]);
            rs = fmaf(wx[b], tv.x, rs);
            rt = fmaf(wx[b], tv.y, rt);
        }
        s = fmaf(wy[a], rs, s);
        t = fmaf(wy[a], rt, t);
    }
    g_s[n] = s;
    g_t[n] = t;
    g_agg2[n] = 0.0f;   // zero for edge2 (runs after this kernel)
}

// ---------------- kernel 3: edge scatter pass 2 (agg2 of t) -----------------
__global__ void k_edge2(const int* __restrict__ src,
                        const int* __restrict__ dst, int E) {
    int e = blockIdx.x * blockDim.x + threadIdx.x;
    if (e < E) {
        atomicAdd(&g_agg2[dst[e]], __ldg(&g_t[src[e]]));
    }
}

// ---------------- kernel 4: out1; A = fp16(tanh(out1)) ----------------------
__global__ void k_node2(const float* __restrict__ b2,
                        float* __restrict__ out, int n_total) {
    int n = blockIdx.x * blockDim.x + threadIdx.x;
    if (n < n_total) {
        float o = g_s[n] + __fdividef(g_agg2[n], fmaxf(g_fd[n].y, 1.0f)) + b2[0];
        out[n] = o;                          // output1
        float h = tanh_exp2(C_2LOG2E * o);
        __half hh = __float2half_rn(h);
        g_Ah[n] = *reinterpret_cast<unsigned short*>(&hh);
    }
}

// ---------------- kernel 5: GEMM partials = h2 @ w3 (fp16, cp.async) --------
// A = fp16(h2) cp.async'd into ldsm-ready stages; B = fp32 cp.async stages
// converted to fp16 smem per chunk. 4 stages, 3 chunk-groups in flight
// (24KB/block outstanding -> DRAM-saturating). Error ~2.9e-4 (gate 1e-3).
#define GEMM_BN 128
#define GEMM_KRANGE (NN / GEMM_KSPLIT)   // 512
#define GEMM_NCHUNK (GEMM_KRANGE / 16)   // 32
#define NSTAGE 4

__device__ __forceinline__ void mma_f16(float c[4], const uint32_t a[4],
                                        const uint32_t b[2]) {
    asm volatile(
        "mma.sync.aligned.m16n8k16.row.col.f32.f16.f16.f32 "
        "{%0,%1,%2,%3}, {%4,%5,%6,%7}, {%8,%9}, {%0,%1,%2,%3};\n"
        : "+f"(c[0]), "+f"(c[1]), "+f"(c[2]), "+f"(c[3])
        : "r"(a[0]), "r"(a[1]), "r"(a[2]), "r"(a[3]), "r"(b[0]), "r"(b[1]));
}
__device__ __forceinline__ void ldsm_x4(uint32_t r[4], uint32_t addr) {
    asm volatile("ldmatrix.sync.aligned.m8n8.x4.shared.b16 {%0,%1,%2,%3}, [%4];"
                 : "=r"(r[0]), "=r"(r[1]), "=r"(r[2]), "=r"(r[3]) : "r"(addr));
}
__device__ __forceinline__ void ldsm_x2t(uint32_t r[2], uint32_t addr) {
    asm volatile("ldmatrix.sync.aligned.m8n8.x2.trans.shared.b16 {%0,%1}, [%2];"
                 : "=r"(r[0]), "=r"(r[1]) : "r"(addr));
}
__device__ __forceinline__ void cp16(uint32_t dst, const void* src) {
    asm volatile("cp.async.cg.shared.global [%0], [%1], 16;"
                 :: "r"(dst), "l"(src) : "memory");
}
__device__ __forceinline__ void cp_commit() {
    asm volatile("cp.async.commit_group;" ::: "memory");
}
__device__ __forceinline__ void cp_wait2() {
    asm volatile("cp.async.wait_group 2;" ::: "memory");
}

__global__ __launch_bounds__(256) void k_gemm(const float* __restrict__ w3) {
    __shared__ __align__(16) unsigned short sA[NSTAGE][MB][16];     // fp16 A (2KB/stage)
    __shared__ __align__(16) float sBf[NSTAGE][16][GEMM_BN];        // fp32 B (8KB/stage)
    __shared__ __align__(16) unsigned short sBh[2][16][GEMM_BN];    // fp16 B (4KB/buf)

    int tid  = threadIdx.x;
    int warp = tid >> 5;
    int lane = tid & 31;
    int g    = lane >> 2;
    int tg   = lane & 3;
    int n0   = blockIdx.x * GEMM_BN;
    int kb   = blockIdx.y * GEMM_KRANGE;

    // cp.async staging coords
    int mA  = tid >> 1, cpA = (tid & 1) * 8;  // A: 128 threads x 16B
    int rB  = tid >> 5, seg = tid & 31;       // B: rows rB, rB+8; 16B segs

    float acc[4][2][4];
#pragma unroll
    for (int mi = 0; mi < 4; mi++)
#pragma unroll
        for (int ni = 0; ni < 2; ni++)
#pragma unroll
            for (int r = 0; r < 4; r++) acc[mi][ni][r] = 0.0f;

    // prologue: issue chunks 0..2 (one commit group each)
#pragma unroll
    for (int ck = 0; ck < NSTAGE - 1; ck++) {
        int st = ck;
        int k0 = kb + ck * 16;
        if (tid < 128)
            cp16((uint32_t)__cvta_generic_to_shared(&sA[st][mA][cpA]),
                 &g_Ah[mA * NN + k0 + cpA]);
        cp16((uint32_t)__cvta_generic_to_shared(&sBf[st][rB][seg * 4]),
             &w3[(size_t)(k0 + rB) * NN + n0 + seg * 4]);
        cp16((uint32_t)__cvta_generic_to_shared(&sBf[st][rB + 8][seg * 4]),
             &w3[(size_t)(k0 + rB + 8) * NN + n0 + seg * 4]);
        cp_commit();
    }

    uint32_t aA = (uint32_t)__cvta_generic_to_shared(
        &sA[0][(lane & 15)][(lane >> 4) * 8]);
    uint32_t aB = (uint32_t)__cvta_generic_to_shared(
        &sBh[0][(lane & 15)][warp * 16]);
    const uint32_t strideAst = MB * 16 * 2;          // 2048
    const uint32_t strideBbuf = 16 * GEMM_BN * 2;    // 4096

#pragma unroll 1
    for (int ck = 0; ck < GEMM_NCHUNK; ck++) {
        int st = ck & (NSTAGE - 1);
        int p  = ck & 1;
        cp_wait2();             // chunk ck complete (2 newer groups pending)
        __syncthreads();        // data visible; prior-iter reads of reused slots done

        // convert B fp32 stage -> fp16 buf (2048 floats; 8/thread)
        {
            const float* sf = &sBf[st][0][0] + tid * 8;
            float4 v0 = *reinterpret_cast<const float4*>(sf);
            float4 v1 = *reinterpret_cast<const float4*>(sf + 4);
            uint4 o;
            o.x = pack_f16x2(v0.x, v0.y);
            o.y = pack_f16x2(v0.z, v0.w);
            o.z = pack_f16x2(v1.x, v1.y);
            o.w = pack_f16x2(v1.z, v1.w);
            *reinterpret_cast<uint4*>(&sBh[p][0][0] + tid * 8) = o;
        }
        __syncthreads();

        uint32_t aH[4][4];
#pragma unroll
        for (int mi = 0; mi < 4; mi++)
            ldsm_x4(aH[mi], aA + st * strideAst + mi * 512);
        uint32_t bH[2][2];
#pragma unroll
        for (int ni = 0; ni < 2; ni++)
            ldsm_x2t(bH[ni], aB + p * strideBbuf + ni * 16);
#pragma unroll
        for (int mi = 0; mi < 4; mi++)
#pragma unroll
            for (int ni = 0; ni < 2; ni++)
                mma_f16(acc[mi][ni], aH[mi], bH[ni]);

        // issue chunk ck+3 into slot (ck+3)&3 (safe: its last reads were
        // iter ck-1, retired by this iteration's first barrier)
        if (ck + NSTAGE - 1 < GEMM_NCHUNK) {
            int st2 = (ck + NSTAGE - 1) & (NSTAGE - 1);
            int k0 = kb + (ck + NSTAGE - 1) * 16;
            if (tid < 128)
                cp16((uint32_t)__cvta_generic_to_shared(&sA[st2][mA][cpA]),
                     &g_Ah[mA * NN + k0 + cpA]);
            cp16((uint32_t)__cvta_generic_to_shared(&sBf[st2][rB][seg * 4]),
                 &w3[(size_t)(k0 + rB) * NN + n0 + seg * 4]);
            cp16((uint32_t)__cvta_generic_to_shared(&sBf[st2][rB + 8][seg * 4]),
                 &w3[(size_t)(k0 + rB + 8) * NN + n0 + seg * 4]);
        }
        cp_commit();   // always commit (empty tail groups keep wait math exact)
    }

    // epilogue: plain v2 stores into this split's partial slab (no atomics)
    float* part = g_part + (size_t)blockIdx.y * N_TOTAL;
#pragma unroll
    for (int mi = 0; mi < 4; mi++) {
        int row = mi * 16 + g;
#pragma unroll
        for (int ni = 0; ni < 2; ni++) {
            int col = n0 + warp * 16 + ni * 8 + 2 * tg;
            *reinterpret_cast<float2*>(&part[(size_t)row * NN + col]) =
                make_float2(acc[mi][ni][0], acc[mi][ni][1]);
            *reinterpret_cast<float2*>(&part[(size_t)(row + 8) * NN + col]) =
                make_float2(acc[mi][ni][2], acc[mi][ni][3]);
        }
    }
}

// ---------------- kernel 6: reduce split-K partials + b3 --------------------
__global__ void k_red(const float* __restrict__ b3,
                      float* __restrict__ out2, int n4) {  // n4 = N_TOTAL/4
    int i = blockIdx.x * blockDim.x + threadIdx.x;
    if (i < n4) {
        float4 a = reinterpret_cast<const float4*>(b3)[i & (NN / 4 - 1)];
#pragma unroll
        for (int j = 0; j < GEMM_KSPLIT; j++) {
            float4 pv = reinterpret_cast<const float4*>(g_part)[(size_t)j * (N_TOTAL / 4) + i];
            a.x += pv.x; a.y += pv.y; a.z += pv.z; a.w += pv.w;
        }
        reinterpret_cast<float4*>(out2)[i] = a;
    }
}

// ---------------- launch ----------------------------------------------------
extern "C" void kernel_launch(void* const* d_in, const int* in_sizes, int n_in,
                              void* d_out, int out_size) {
    const float* feat = (const float*)d_in[0];
    const int*   src  = (const int*)d_in[1];
    const int*   dst  = (const int*)d_in[2];
    const float* ws1  = (const float*)d_in[3];
    const float* wn1  = (const float*)d_in[4];
    const float* b1   = (const float*)d_in[5];
    const float* ws2  = (const float*)d_in[6];
    const float* wn2  = (const float*)d_in[7];
    const float* b2   = (const float*)d_in[8];
    const float* w3   = (const float*)d_in[9];
    const float* b3   = (const float*)d_in[10];
    float* out = (float*)d_out;

    int N = in_sizes[0];   // 262144
    int E = in_sizes[1];   // 2097152

    // side stream: table build only (tiny; overlapped with zero+edge1)
    cudaStream_t s2;
    cudaStreamCreateWithFlags(&s2, cudaStreamNonBlocking);
    cudaEvent_t eF, eJ;
    cudaEventCreateWithFlags(&eF, cudaEventDisableTiming);
    cudaEventCreateWithFlags(&eJ, cudaEventDisableTiming);

    cudaEventRecord(eF, 0);
    cudaStreamWaitEvent(s2, eF, 0);
    k_tab<<<(TAB_N * TAB_N + 255) / 256, 256, 0, s2>>>(ws1, wn1, b1, ws2, wn2);
    cudaEventRecord(eJ, s2);

    k_zero<<<(N / 4 + 255) / 256, 256>>>(N / 4);
    k_edge1<<<(E + 255) / 256, 256>>>(feat, src, dst, E);

    cudaStreamWaitEvent(0, eJ, 0);
    k_node1<<<(N + 255) / 256, 256>>>(feat, N);
    k_edge2<<<(E + 255) / 256, 256>>>(src, dst, E);
    k_node2<<<(N + 255) / 256, 256>>>(b2, out, N);

    dim3 grid(NN / GEMM_BN, GEMM_KSPLIT);
    k_gemm<<<grid, 256>>>(w3);
    k_red<<<(N / 4 + 255) / 256, 256>>>(b3, out + N, N / 4);
}

// round 16
// speedup vs baseline: 1.5164x; 1.0505x over previous
#include <cuda_runtime.h>
#include <cuda_fp16.h>
#include <cstdint>

// Shapes (fixed for this problem)
#define N_TOTAL (64 * 4096)      // 262144 nodes
#define NHID    128
#define NN      4096             // nodes per graph == w3 dim
#define MB      64               // batch (graphs)

// table for s(f,g), t(f,g): range [-6,6]^2, h = 3/32, 129x129 points
#define TAB_N    129
#define TAB_LO   (-6.0f)
#define TAB_INVH (32.0f / 3.0f)

// ---------------- scratch (device globals; no allocation allowed) ----------
__device__ __align__(16) float2 g_fd [N_TOTAL];   // {agg1, deg} interleaved
__device__ __align__(16) float g_s   [N_TOTAL];
__device__ __align__(16) float g_t   [N_TOTAL];
__device__ __align__(16) float g_agg2[N_TOTAL];
#define GEMM_KSPLIT 8
__device__ float g_part[GEMM_KSPLIT * N_TOTAL];        // split-K partials (8MB)
__device__ __align__(16) unsigned short g_Ah[N_TOTAL]; // A = fp16(h2)
__device__ __align__(16) float2 g_tab[TAB_N * TAB_N];  // {s,t} table (133KB)

#define C_2LOG2E 2.88539008177792681f   // 2*log2(e)

__device__ __forceinline__ float ex2f(float x) {
    float e; asm("ex2.approx.f32 %0, %1;" : "=f"(e) : "f"(x)); return e;
}
__device__ __forceinline__ float rcpf(float x) {
    float r; asm("rcp.approx.f32 %0, %1;" : "=f"(r) : "f"(x)); return r;
}
// tanh from prescaled xp = 2*log2e*x : tanh = 1 - 2/(exp2(xp)+1)
__device__ __forceinline__ float tanh_exp2(float xp) {
    return fmaf(-2.0f, rcpf(ex2f(xp) + 1.0f), 1.0f);
}

// pack two floats into one f16x2 register: {lo=a, hi=b}
__device__ __forceinline__ uint32_t pack_f16x2(float a, float b) {
    uint32_t d;
    asm("cvt.rn.f16x2.f32 %0, %1, %2;" : "=r"(d) : "f"(b), "f"(a));
    return d;
}

// ---------------- side-branch: build s/t table (footprint-light) ------------
__global__ void k_tab(const float* __restrict__ ws1, const float* __restrict__ wn1,
                      const float* __restrict__ b1,
                      const float* __restrict__ ws2, const float* __restrict__ wn2) {
    int p = blockIdx.x * blockDim.x + threadIdx.x;
    if (p >= TAB_N * TAB_N) return;
    int fi = p % TAB_N, gi = p / TAB_N;
    float f = TAB_LO + fi * (1.0f / TAB_INVH);
    float g = TAB_LO + gi * (1.0f / TAB_INVH);
    float s = 0.0f, t = 0.0f;
#pragma unroll 4
    for (int j = 0; j < NHID; j++) {
        float xp = C_2LOG2E * fmaf(f, __ldg(&ws1[j]),
                                   fmaf(g, __ldg(&wn1[j]), __ldg(&b1[j])));
        float r = tanh_exp2(xp);
        s = fmaf(r, __ldg(&ws2[j]), s);
        t = fmaf(r, __ldg(&wn2[j]), t);
    }
    g_tab[p] = make_float2(s, t);
}

// ---------------- kernel 0: zero {agg1,deg} only (agg2 zeroed in node1) -----
__global__ void k_zero(int n4) {   // n4 = N_TOTAL/4
    int i = blockIdx.x * blockDim.x + threadIdx.x;
    if (i < n4) {
        float4 z = make_float4(0.f, 0.f, 0.f, 0.f);
        reinterpret_cast<float4*>(g_fd)[2 * i]     = z;
        reinterpret_cast<float4*>(g_fd)[2 * i + 1] = z;
    }
}

// ---------------- kernel 1: edge scatter pass 1 ({agg1,deg} v2 red) ---------
__global__ void k_edge1(const float* __restrict__ feat,
                        const int* __restrict__ src,
                        const int* __restrict__ dst, int E) {
    int e = blockIdx.x * blockDim.x + threadIdx.x;
    if (e < E) {
        int s = src[e];
        int d = dst[e];
        float v = __ldg(&feat[s]);
        asm volatile("red.global.add.v2.f32 [%0], {%1, %2};"
                     :: "l"(g_fd + d), "f"(v), "f"(1.0f) : "memory");
    }
}

// ---------------- kernel 2: s,t bicubic lookup, 2 nodes/thread --------------
__device__ __forceinline__ void cubic_w(float x, float w[4]) {
    float xm1 = x - 1.0f, xm2 = x - 2.0f, xp1 = x + 1.0f;
    float a = xm1 * xm2;
    float b = xp1 * x;
    w[0] = -x * a * (1.0f / 6.0f);
    w[1] = xp1 * a * 0.5f;
    w[2] = -b * xm2 * 0.5f;
    w[3] = b * xm1 * (1.0f / 6.0f);
}

__global__ __launch_bounds__(256) void k_node1(const float* __restrict__ feat,
                                               int n2) {   // n2 = N_TOTAL/2
    int i = blockIdx.x * blockDim.x + threadIdx.x;
    if (i >= n2) return;

    float2 f2 = __ldg(&reinterpret_cast<const float2*>(feat)[i]);
    float4 fd = reinterpret_cast<const float4*>(g_fd)[i];

    float fv[2] = {f2.x, f2.y};
    float gv[2] = {__fdividef(fd.x, fmaxf(fd.y, 1.0f)),
                   __fdividef(fd.z, fmaxf(fd.w, 1.0f))};

    float2 taps[2][16];
    float wxv[2][4], wyv[2][4];
#pragma unroll
    for (int u = 0; u < 2; u++) {
        float uu = fminf(fmaxf((fv[u] - TAB_LO) * TAB_INVH, 1.0f),
                         (float)(TAB_N - 3) - 1e-3f);
        float vv = fminf(fmaxf((gv[u] - TAB_LO) * TAB_INVH, 1.0f),
                         (float)(TAB_N - 3) - 1e-3f);
        int iu = (int)uu;  float x = uu - iu;
        int iv = (int)vv;  float y = vv - iv;
        cubic_w(x, wxv[u]);
        cubic_w(y, wyv[u]);
        const float2* base = g_tab + (iv - 1) * TAB_N + (iu - 1);
#pragma unroll
        for (int a = 0; a < 4; a++)
#pragma unroll
            for (int b = 0; b < 4; b++)
                taps[u][a * 4 + b] = __ldg(base + a * TAB_N + b);
    }

    float2 so, to;
    float* sp = &so.x;
    float* tp = &to.x;
#pragma unroll
    for (int u = 0; u < 2; u++) {
        float s = 0.0f, t = 0.0f;
#pragma unroll
        for (int a = 0; a < 4; a++) {
            float rs = 0.0f, rt = 0.0f;
#pragma unroll
            for (int b = 0; b < 4; b++) {
                float2 tv = taps[u][a * 4 + b];
                rs = fmaf(wxv[u][b], tv.x, rs);
                rt = fmaf(wxv[u][b], tv.y, rt);
            }
            s = fmaf(wyv[u][a], rs, s);
            t = fmaf(wyv[u][a], rt, t);
        }
        sp[u] = s;
        tp[u] = t;
    }
    reinterpret_cast<float2*>(g_s)[i] = so;
    reinterpret_cast<float2*>(g_t)[i] = to;
    reinterpret_cast<float2*>(g_agg2)[i] = make_float2(0.f, 0.f);
}

// ---------------- kernel 3: edge scatter pass 2 (agg2 of t) -----------------
__global__ void k_edge2(const int* __restrict__ src,
                        const int* __restrict__ dst, int E) {
    int e = blockIdx.x * blockDim.x + threadIdx.x;
    if (e < E) {
        atomicAdd(&g_agg2[dst[e]], __ldg(&g_t[src[e]]));
    }
}

// ---------------- kernel 4: out1; A = fp16(tanh(out1)) ----------------------
__global__ void k_node2(const float* __restrict__ b2,
                        float* __restrict__ out, int n_total) {
    int n = blockIdx.x * blockDim.x + threadIdx.x;
    if (n < n_total) {
        float o = g_s[n] + __fdividef(g_agg2[n], fmaxf(g_fd[n].y, 1.0f)) + b2[0];
        out[n] = o;                          // output1
        float h = tanh_exp2(C_2LOG2E * o);
        __half hh = __float2half_rn(h);
        g_Ah[n] = *reinterpret_cast<unsigned short*>(&hh);
    }
}

// ---------------- kernel 5: GEMM partials = h2 @ w3 (fp16, deep cp.async) ---
// 6 stages, 5 chunk-groups in flight (40KB/block); ONE block barrier per
// chunk: each warp converts exactly the B sub-tile it ldsm-reads (warp-
// local, __syncwarp only). Padded rows kill bank conflicts.
#define GEMM_BN 128
#define GEMM_KRANGE (NN / GEMM_KSPLIT)   // 512
#define GEMM_NCHUNK (GEMM_KRANGE / 16)   // 32
#define NSTAGE 6
#define BF_LD 132    // floats per padded Bf row
#define BH_LD 136    // ushorts per padded Bh row

struct GemmSmem {
    unsigned short A[NSTAGE][MB][16];      // 12 KB (fp16, ldsm-ready)
    float Bf[NSTAGE][16][BF_LD];           // ~49.5 KB (fp32 stages)
    unsigned short Bh[2][16][BH_LD];       // ~8.5 KB (fp16 double buffer)
};
#define SMEM_GEMM_BYTES (sizeof(GemmSmem))

__device__ __forceinline__ void mma_f16(float c[4], const uint32_t a[4],
                                        const uint32_t b[2]) {
    asm volatile(
        "mma.sync.aligned.m16n8k16.row.col.f32.f16.f16.f32 "
        "{%0,%1,%2,%3}, {%4,%5,%6,%7}, {%8,%9}, {%0,%1,%2,%3};\n"
        : "+f"(c[0]), "+f"(c[1]), "+f"(c[2]), "+f"(c[3])
        : "r"(a[0]), "r"(a[1]), "r"(a[2]), "r"(a[3]), "r"(b[0]), "r"(b[1]));
}
__device__ __forceinline__ void ldsm_x4(uint32_t r[4], uint32_t addr) {
    asm volatile("ldmatrix.sync.aligned.m8n8.x4.shared.b16 {%0,%1,%2,%3}, [%4];"
                 : "=r"(r[0]), "=r"(r[1]), "=r"(r[2]), "=r"(r[3]) : "r"(addr));
}
__device__ __forceinline__ void ldsm_x2t(uint32_t r[2], uint32_t addr) {
    asm volatile("ldmatrix.sync.aligned.m8n8.x2.trans.shared.b16 {%0,%1}, [%2];"
                 : "=r"(r[0]), "=r"(r[1]) : "r"(addr));
}
__device__ __forceinline__ void cp16(uint32_t dst, const void* src) {
    asm volatile("cp.async.cg.shared.global [%0], [%1], 16;"
                 :: "r"(dst), "l"(src) : "memory");
}
__device__ __forceinline__ void cp_commit() {
    asm volatile("cp.async.commit_group;" ::: "memory");
}
__device__ __forceinline__ void cp_wait4() {
    asm volatile("cp.async.wait_group 4;" ::: "memory");
}

__global__ __launch_bounds__(256) void k_gemm(const float* __restrict__ w3) {
    extern __shared__ __align__(16) char smem_raw[];
    GemmSmem* S = reinterpret_cast<GemmSmem*>(smem_raw);

    int tid  = threadIdx.x;
    int warp = tid >> 5;
    int lane = tid & 31;
    int g    = lane >> 2;
    int tg   = lane & 3;
    int n0   = blockIdx.x * GEMM_BN;
    int kb   = blockIdx.y * GEMM_KRANGE;

    // cp.async staging coords
    int mA  = tid >> 1, cpA = (tid & 1) * 8;  // A: 128 threads x 16B
    int rB  = tid >> 5, seg = tid & 31;       // B: rows rB, rB+8; 16B segs

    float acc[4][2][4];
#pragma unroll
    for (int mi = 0; mi < 4; mi++)
#pragma unroll
        for (int ni = 0; ni < 2; ni++)
#pragma unroll
            for (int r = 0; r < 4; r++) acc[mi][ni][r] = 0.0f;

    // prologue: issue chunks 0..4
#pragma unroll
    for (int ck = 0; ck < NSTAGE - 1; ck++) {
        int k0 = kb + ck * 16;
        if (tid < 128)
            cp16((uint32_t)__cvta_generic_to_shared(&S->A[ck][mA][cpA]),
                 &g_Ah[mA * NN + k0 + cpA]);
        cp16((uint32_t)__cvta_generic_to_shared(&S->Bf[ck][rB][seg * 4]),
             &w3[(size_t)(k0 + rB) * NN + n0 + seg * 4]);
        cp16((uint32_t)__cvta_generic_to_shared(&S->Bf[ck][rB + 8][seg * 4]),
             &w3[(size_t)(k0 + rB + 8) * NN + n0 + seg * 4]);
        cp_commit();
    }

    uint32_t aA = (uint32_t)__cvta_generic_to_shared(
        &S->A[0][(lane & 15)][(lane >> 4) * 8]);
    uint32_t aB = (uint32_t)__cvta_generic_to_shared(
        &S->Bh[0][(lane & 15)][warp * 16]);
    const uint32_t strideAst = MB * 16 * 2;          // 2048
    const uint32_t strideBbuf = 16 * BH_LD * 2;      // bytes per Bh buffer

    // per-warp B conversion coords: rows lane>>1, col half (lane&1)*8
    int cvRow = lane >> 1;
    int cvCol = warp * 16 + (lane & 1) * 8;

#pragma unroll 1
    for (int ck = 0; ck < GEMM_NCHUNK; ck++) {
        int st = ck % NSTAGE;
        int p  = ck & 1;
        cp_wait4();             // chunk ck complete (4 newer groups pending)
        __syncthreads();        // A/Bf visible; prior reads of reused slots done

        // warp-local B convert: exactly the region this warp ldsm-reads
        {
            const float* sf = &S->Bf[st][cvRow][cvCol];
            float4 v0 = *reinterpret_cast<const float4*>(sf);
            float4 v1 = *reinterpret_cast<const float4*>(sf + 4);
            uint4 o;
            o.x = pack_f16x2(v0.x, v0.y);
            o.y = pack_f16x2(v0.z, v0.w);
            o.z = pack_f16x2(v1.x, v1.y);
            o.w = pack_f16x2(v1.z, v1.w);
            *reinterpret_cast<uint4*>(&S->Bh[p][cvRow][cvCol]) = o;
        }
        __syncwarp();

        uint32_t aH[4][4];
#pragma unroll
        for (int mi = 0; mi < 4; mi++)
            ldsm_x4(aH[mi], aA + st * strideAst + mi * 512);
        uint32_t bH[2][2];
#pragma unroll
        for (int ni = 0; ni < 2; ni++)
            ldsm_x2t(bH[ni], aB + p * strideBbuf + ni * 16);
#pragma unroll
        for (int mi = 0; mi < 4; mi++)
#pragma unroll
            for (int ni = 0; ni < 2; ni++)
                mma_f16(acc[mi][ni], aH[mi], bH[ni]);

        // issue chunk ck+5 into slot (ck+5)%6
        if (ck + NSTAGE - 1 < GEMM_NCHUNK) {
            int st2 = (ck + NSTAGE - 1) % NSTAGE;
            int k0 = kb + (ck + NSTAGE - 1) * 16;
            if (tid < 128)
                cp16((uint32_t)__cvta_generic_to_shared(&S->A[st2][mA][cpA]),
                     &g_Ah[mA * NN + k0 + cpA]);
            cp16((uint32_t)__cvta_generic_to_shared(&S->Bf[st2][rB][seg * 4]),
                 &w3[(size_t)(k0 + rB) * NN + n0 + seg * 4]);
            cp16((uint32_t)__cvta_generic_to_shared(&S->Bf[st2][rB + 8][seg * 4]),
                 &w3[(size_t)(k0 + rB + 8) * NN + n0 + seg * 4]);
        }
        cp_commit();   // uniform commit keeps wait_group arithmetic exact
    }

    // epilogue: plain v2 stores into this split's partial slab (no atomics)
    float* part = g_part + (size_t)blockIdx.y * N_TOTAL;
#pragma unroll
    for (int mi = 0; mi < 4; mi++) {
        int row = mi * 16 + g;
#pragma unroll
        for (int ni = 0; ni < 2; ni++) {
            int col = n0 + warp * 16 + ni * 8 + 2 * tg;
            *reinterpret_cast<float2*>(&part[(size_t)row * NN + col]) =
                make_float2(acc[mi][ni][0], acc[mi][ni][1]);
            *reinterpret_cast<float2*>(&part[(size_t)(row + 8) * NN + col]) =
                make_float2(acc[mi][ni][2], acc[mi][ni][3]);
        }
    }
}

// ---------------- kernel 6: reduce split-K partials + b3 --------------------
__global__ void k_red(const float* __restrict__ b3,
                      float* __restrict__ out2, int n4) {  // n4 = N_TOTAL/4
    int i = blockIdx.x * blockDim.x + threadIdx.x;
    if (i < n4) {
        float4 a = reinterpret_cast<const float4*>(b3)[i & (NN / 4 - 1)];
#pragma unroll
        for (int j = 0; j < GEMM_KSPLIT; j++) {
            float4 pv = reinterpret_cast<const float4*>(g_part)[(size_t)j * (N_TOTAL / 4) + i];
            a.x += pv.x; a.y += pv.y; a.z += pv.z; a.w += pv.w;
        }
        reinterpret_cast<float4*>(out2)[i] = a;
    }
}

// ---------------- launch ----------------------------------------------------
extern "C" void kernel_launch(void* const* d_in, const int* in_sizes, int n_in,
                              void* d_out, int out_size) {
    const float* feat = (const float*)d_in[0];
    const int*   src  = (const int*)d_in[1];
    const int*   dst  = (const int*)d_in[2];
    const float* ws1  = (const float*)d_in[3];
    const float* wn1  = (const float*)d_in[4];
    const float* b1   = (const float*)d_in[5];
    const float* ws2  = (const float*)d_in[6];
    const float* wn2  = (const float*)d_in[7];
    const float* b2   = (const float*)d_in[8];
    const float* w3   = (const float*)d_in[9];
    const float* b3   = (const float*)d_in[10];
    float* out = (float*)d_out;

    int N = in_sizes[0];   // 262144
    int E = in_sizes[1];   // 2097152

    cudaFuncSetAttribute(k_gemm, cudaFuncAttributeMaxDynamicSharedMemorySize,
                         (int)SMEM_GEMM_BYTES);

    // side stream: table build only (tiny; overlapped with zero+edge1)
    cudaStream_t s2;
    cudaStreamCreateWithFlags(&s2, cudaStreamNonBlocking);
    cudaEvent_t eF, eJ;
    cudaEventCreateWithFlags(&eF, cudaEventDisableTiming);
    cudaEventCreateWithFlags(&eJ, cudaEventDisableTiming);

    cudaEventRecord(eF, 0);
    cudaStreamWaitEvent(s2, eF, 0);
    k_tab<<<(TAB_N * TAB_N + 255) / 256, 256, 0, s2>>>(ws1, wn1, b1, ws2, wn2);
    cudaEventRecord(eJ, s2);

    k_zero<<<(N / 4 + 255) / 256, 256>>>(N / 4);
    k_edge1<<<(E + 255) / 256, 256>>>(feat, src, dst, E);

    cudaStreamWaitEvent(0, eJ, 0);
    k_node1<<<(N / 2 + 255) / 256, 256>>>(feat, N / 2);
    k_edge2<<<(E + 255) / 256, 256>>>(src, dst, E);
    k_node2<<<(N + 255) / 256, 256>>>(b2, out, N);

    dim3 grid(NN / GEMM_BN, GEMM_KSPLIT);
    k_gemm<<<grid, 256, SMEM_GEMM_BYTES>>>(w3);
    k_red<<<(N / 4 + 255) / 256, 256>>>(b3, out + N, N / 4);
}